// round 1
// baseline (speedup 1.0000x reference)
#include <cuda_runtime.h>
#include <math.h>

// Problem shapes (fixed by dataset)
#define BB 2
#define NN 512
#define MM 512
#define DD 256
#define HEADS 64          // D/4
#define KF 640            // heads * 10 symmetric features
#define RTOT (BB*NN)      // 1024 rows per feature matrix

// Scratch layout in one big __device__ buffer
#define OFF_VQ 0
#define OFF_TQ (OFF_VQ + (size_t)BB*NN*DD)          // 262144
#define OFF_FV (OFF_TQ + (size_t)BB*MM*DD)          // 524288
#define OFF_FT (OFF_FV + (size_t)BB*NN*KF)          // 1179648
#define OFF_S  (OFF_FT + (size_t)BB*MM*KF)          // 1835008
#define SCRATCH_FLOATS (OFF_S + (size_t)BB*NN*MM)   // 2359296

__device__ __align__(16) float g_scratch[SCRATCH_FLOATS];

// ---------------------------------------------------------------------------
// Generic tiled fp32 GEMM:  C[i,j] = sum_k A(i,k) * B(j,k)
//   ATrans=false: A(i,k)=A[i*lda+k]   ATrans=true: A(i,k)=A[k*lda+i]
//   BTrans=false: B(j,k)=B[j*ldb+k]   BTrans=true: B(j,k)=B[k*ldb+j]
// EPI: 0 = plain store
//      1 = add bias (aux[col]) then quaternion-normalize groups of 4 cols
//      2 = C = aux_base[row,col] + (*hptr) * acc   (residual)
// Tile 64x64, BK=32, 256 threads (16x16), 4x4 micro-tile; thread owns 4
// CONSECUTIVE columns so EPI 1 can normalize its own quats locally.
// ---------------------------------------------------------------------------
#define BMT 64
#define BNT 64
#define BKT 32
#define PADT 4

template <bool ATrans, bool BTrans, int EPI>
__global__ void __launch_bounds__(256)
gemm_k(const float* __restrict__ A, const float* __restrict__ B,
       float* __restrict__ C, int Kdim, int lda, int ldb, int ldc,
       long sA, long sB, long sC,
       const float* __restrict__ aux, long sAux,
       const float* __restrict__ hptr)
{
    __shared__ __align__(16) float As[BKT][BMT + PADT];
    __shared__ __align__(16) float Bs[BKT][BNT + PADT];

    const int z = blockIdx.z;
    A += (long)z * sA;
    B += (long)z * sB;
    C += (long)z * sC;
    const float* base = aux;
    if (EPI == 2) base += (long)z * sAux;

    const int tid = threadIdx.x;
    const int tx = tid & 15;        // column group
    const int ty = tid >> 4;        // row group
    const int rowBase = blockIdx.y * BMT;
    const int colBase = blockIdx.x * BNT;

    float acc[4][4];
#pragma unroll
    for (int r = 0; r < 4; r++)
#pragma unroll
        for (int c = 0; c < 4; c++) acc[r][c] = 0.0f;

    for (int k0 = 0; k0 < Kdim; k0 += BKT) {
        // ---- load A tile into As[k][i] ----
        if (!ATrans) {
            const int i  = tid >> 3;          // 0..31
            const int kq = (tid & 7) * 4;     // 0..28
#pragma unroll
            for (int p = 0; p < 2; p++) {
                float4 v = *(const float4*)(A + (long)(rowBase + i + p * 32) * lda + k0 + kq);
                As[kq + 0][i + p * 32] = v.x;
                As[kq + 1][i + p * 32] = v.y;
                As[kq + 2][i + p * 32] = v.z;
                As[kq + 3][i + p * 32] = v.w;
            }
        } else {
            const int k  = tid >> 4;          // 0..15
            const int iq = (tid & 15) * 4;    // 0..60
#pragma unroll
            for (int p = 0; p < 2; p++) {
                float4 v = *(const float4*)(A + (long)(k0 + k + p * 16) * lda + rowBase + iq);
                *(float4*)&As[k + p * 16][iq] = v;
            }
        }
        // ---- load B tile into Bs[k][j] ----
        if (!BTrans) {
            const int j  = tid >> 3;
            const int kq = (tid & 7) * 4;
#pragma unroll
            for (int p = 0; p < 2; p++) {
                float4 v = *(const float4*)(B + (long)(colBase + j + p * 32) * ldb + k0 + kq);
                Bs[kq + 0][j + p * 32] = v.x;
                Bs[kq + 1][j + p * 32] = v.y;
                Bs[kq + 2][j + p * 32] = v.z;
                Bs[kq + 3][j + p * 32] = v.w;
            }
        } else {
            const int k  = tid >> 4;
            const int jq = (tid & 15) * 4;
#pragma unroll
            for (int p = 0; p < 2; p++) {
                float4 v = *(const float4*)(B + (long)(k0 + k + p * 16) * ldb + colBase + jq);
                *(float4*)&Bs[k + p * 16][jq] = v;
            }
        }
        __syncthreads();

#pragma unroll
        for (int kk = 0; kk < BKT; kk++) {
            float4 av = *(const float4*)&As[kk][ty * 4];
            float4 bv = *(const float4*)&Bs[kk][tx * 4];
            float a_[4] = {av.x, av.y, av.z, av.w};
            float b_[4] = {bv.x, bv.y, bv.z, bv.w};
#pragma unroll
            for (int r = 0; r < 4; r++)
#pragma unroll
                for (int c = 0; c < 4; c++) acc[r][c] += a_[r] * b_[c];
        }
        __syncthreads();
    }

    const int row0 = rowBase + ty * 4;
    const int col0 = colBase + tx * 4;

    if (EPI == 0) {
#pragma unroll
        for (int r = 0; r < 4; r++) {
            float4 o = make_float4(acc[r][0], acc[r][1], acc[r][2], acc[r][3]);
            *(float4*)(C + (long)(row0 + r) * ldc + col0) = o;
        }
    } else if (EPI == 1) {
        float4 bb = *(const float4*)(aux + col0);
#pragma unroll
        for (int r = 0; r < 4; r++) {
            float qw = acc[r][0] + bb.x;
            float qx = acc[r][1] + bb.y;
            float qy = acc[r][2] + bb.z;
            float qz = acc[r][3] + bb.w;
            float nrm = sqrtf(qw * qw + qx * qx + qy * qy + qz * qz);
            float inv = 1.0f / (nrm + 1e-8f);
            float4 o = make_float4(qw * inv, qx * inv, qy * inv, qz * inv);
            *(float4*)(C + (long)(row0 + r) * ldc + col0) = o;
        }
    } else {
        float h = *hptr;
#pragma unroll
        for (int r = 0; r < 4; r++) {
            float4 bs = *(const float4*)(base + (long)(row0 + r) * ldc + col0);
            float4 o = make_float4(bs.x + h * acc[r][0], bs.y + h * acc[r][1],
                                   bs.z + h * acc[r][2], bs.w + h * acc[r][3]);
            *(float4*)(C + (long)(row0 + r) * ldc + col0) = o;
        }
    }
}

// ---------------------------------------------------------------------------
// Feature expansion: for each (row, head) quat q, emit the 10 symmetric
// products. mult=1 folds the 2x off-diagonal weight (applied on text side).
// ---------------------------------------------------------------------------
__global__ void __launch_bounds__(256)
feat_k(const float4* __restrict__ Q, float* __restrict__ F, int mult)
{
    int idx = blockIdx.x * 256 + threadIdx.x;       // (row*64 + head), total RTOT*64
    float4 q = Q[idx];
    int row = idx >> 6;
    int h = idx & 63;
    float m2 = mult ? 2.0f : 1.0f;
    float* o = F + (size_t)row * KF + h * 10;
    o[0] = q.x * q.x;
    o[1] = m2 * q.x * q.y;
    o[2] = m2 * q.x * q.z;
    o[3] = m2 * q.x * q.w;
    o[4] = q.y * q.y;
    o[5] = m2 * q.y * q.z;
    o[6] = m2 * q.y * q.w;
    o[7] = q.z * q.z;
    o[8] = m2 * q.z * q.w;
    o[9] = q.w * q.w;
}

// ---------------------------------------------------------------------------
// Row softmax over M=512 (in place). Logits = S / 1024  ( = mean_h / sqrt(D) ).
// ---------------------------------------------------------------------------
__global__ void __launch_bounds__(256)
softmax_k(float* __restrict__ S)
{
    const float SC = 1.0f / 1024.0f;
    float* p = S + (size_t)blockIdx.x * MM;
    int t = threadIdx.x;
    float a = p[t] * SC;
    float b = p[t + 256] * SC;

    __shared__ float red[8];
    float m = fmaxf(a, b);
#pragma unroll
    for (int o = 16; o > 0; o >>= 1) m = fmaxf(m, __shfl_xor_sync(0xffffffffu, m, o));
    if ((t & 31) == 0) red[t >> 5] = m;
    __syncthreads();
    if (t < 32) {
        float v = (t < 8) ? red[t] : -3.0e38f;
#pragma unroll
        for (int o = 4; o > 0; o >>= 1) v = fmaxf(v, __shfl_xor_sync(0xffffffffu, v, o));
        if (t == 0) red[0] = v;
    }
    __syncthreads();
    float Mx = red[0];
    __syncthreads();

    float e1 = __expf(a - Mx);
    float e2 = __expf(b - Mx);
    float s = e1 + e2;
#pragma unroll
    for (int o = 16; o > 0; o >>= 1) s += __shfl_xor_sync(0xffffffffu, s, o);
    if ((t & 31) == 0) red[t >> 5] = s;
    __syncthreads();
    if (t < 32) {
        float v = (t < 8) ? red[t] : 0.0f;
#pragma unroll
        for (int o = 4; o > 0; o >>= 1) v += __shfl_xor_sync(0xffffffffu, v, o);
        if (t == 0) red[0] = v;
    }
    __syncthreads();
    float inv = 1.0f / red[0];
    p[t] = e1 * inv;
    p[t + 256] = e2 * inv;
}

// ---------------------------------------------------------------------------
extern "C" void kernel_launch(void* const* d_in, const int* in_sizes, int n_in,
                              void* d_out, int out_size)
{
    (void)in_sizes; (void)n_in; (void)out_size;

    const float* vision = (const float*)d_in[0];  // (B,N,D)
    const float* text   = (const float*)d_in[1];  // (B,M,D)
    const float* Wv     = (const float*)d_in[2];  // (D,D)
    const float* bv     = (const float*)d_in[3];  // (D,)
    const float* Wt     = (const float*)d_in[4];  // (D,D)
    const float* bt     = (const float*)d_in[5];  // (D,)
    const float* hp     = (const float*)d_in[6];  // scalar

    float* outv = (float*)d_out;                          // (B,N,D)
    float* outt = outv + (size_t)BB * NN * DD;            // (B,M,D)

    float* scr = nullptr;
    cudaGetSymbolAddress((void**)&scr, g_scratch);
    float* Vq = scr + OFF_VQ;
    float* Tq = scr + OFF_TQ;
    float* Fv = scr + OFF_FV;
    float* Ft = scr + OFF_FT;
    float* S  = scr + OFF_S;

    // 1) Projections + quaternion normalize.  C[r,d] = sum_k X[r,k]*W[d,k] + b[d]
    {
        dim3 grid(DD / BNT, RTOT / BMT, 1);
        gemm_k<false, false, 1><<<grid, 256>>>(vision, Wv, Vq, DD, DD, DD, DD,
                                               0, 0, 0, bv, 0, nullptr);
        gemm_k<false, false, 1><<<grid, 256>>>(text, Wt, Tq, DD, DD, DD, DD,
                                               0, 0, 0, bt, 0, nullptr);
    }

    // 2) Symmetric outer-product features
    feat_k<<<RTOT * HEADS / 256, 256>>>((const float4*)Vq, Fv, 0);
    feat_k<<<RTOT * HEADS / 256, 256>>>((const float4*)Tq, Ft, 1);

    // 3) Score GEMM: S[b,n,m] = sum_k Fv[b,n,k] * Ft[b,m,k]
    {
        dim3 grid(MM / BNT, NN / BMT, BB);
        gemm_k<false, false, 0><<<grid, 256>>>(Fv, Ft, S, KF, KF, KF, MM,
                                               (long)NN * KF, (long)MM * KF,
                                               (long)NN * MM, nullptr, 0, nullptr);
    }

    // 4) Softmax over m (in place), logits scaled by 1/1024
    softmax_k<<<BB * NN, 256>>>(S);

    // 5) out_vision = vision + h * (A @ text)
    {
        dim3 grid(DD / BNT, NN / BMT, BB);
        gemm_k<false, true, 2><<<grid, 256>>>(S, text, outv, MM, MM, DD, DD,
                                              (long)NN * MM, (long)MM * DD,
                                              (long)NN * DD, vision,
                                              (long)NN * DD, hp);
    }
    // 6) out_text = text + h * (A^T @ vision)
    {
        dim3 grid(DD / BNT, MM / BMT, BB);
        gemm_k<true, true, 2><<<grid, 256>>>(S, vision, outt, NN, MM, DD, DD,
                                             (long)NN * MM, (long)NN * DD,
                                             (long)MM * DD, text,
                                             (long)MM * DD, hp);
    }
}

// round 2
// speedup vs baseline: 1.0729x; 1.0729x over previous
#include <cuda_runtime.h>
#include <math.h>

// Problem shapes (fixed by dataset)
#define BB 2
#define NN 512
#define MM 512
#define DD 256
#define HEADS 64
#define KF 640            // heads * 10 symmetric features
#define RTOT (BB*NN)      // 1024 projection rows

// Scratch
#define OFF_FV 0
#define OFF_FT (OFF_FV + (size_t)RTOT*KF)            // 655360
#define OFF_S  (OFF_FT + (size_t)RTOT*KF)            // 1310720
#define SCRATCH_FLOATS (OFF_S + (size_t)BB*NN*MM)    // 1835008

__device__ __align__(16) float g_scratch[SCRATCH_FLOATS];

__device__ __forceinline__ unsigned f2tf32(float x) {
    unsigned r;
    asm("cvt.rna.tf32.f32 %0, %1;" : "=r"(r) : "f"(x));
    return r;
}

// ---------------------------------------------------------------------------
// Tensor-core GEMM: C[i,j] = sum_k A(i,k) * B(j,k)      (tf32 mma, fp32 accum)
//   ATrans=false: A(i,k)=A[i*lda+k]   ATrans=true: A(i,k)=A[k*lda+i]
//   BTrans analogous.
// EPI: 0 plain store
//      1 quat-normalize (bias aux[col]) + 10-feature expansion into Fout
//      2 residual: C = aux[row,col] + (*hptr)*acc
// CTA tile 64x64, BK=32, 128 threads (4 warps, 2x2 warp grid, 32x32/warp).
// ---------------------------------------------------------------------------
#define BM 64
#define BN 64
#define BK 32
#define SPAD 36   // smem row pitch (uint32) — makes frag reads conflict-free

union SMem {
    struct { unsigned As[BM][SPAD]; unsigned Bs[BN][SPAD]; } ab;
    float Cs[64][68];
};

template <bool ATrans, bool BTrans, int EPI>
__global__ void __launch_bounds__(128)
tgemm(const float* __restrict__ A, const float* __restrict__ B,
      float* __restrict__ C, int Kdim, int lda, int ldb, int ldc,
      long sA, long sB, long sC,
      const float* __restrict__ aux, long sAux,
      const float* __restrict__ hptr, float fmult)
{
    __shared__ SMem sm;

    const int z = blockIdx.z;
    A += (long)z * sA;
    B += (long)z * sB;
    C += (long)z * sC;
    const float* base = aux;
    if (EPI == 2) base += (long)z * sAux;

    const int tid  = threadIdx.x;
    const int lane = tid & 31;
    const int wid  = tid >> 5;
    const int wm   = wid >> 1;       // warp row  (0..1)
    const int wn   = wid & 1;        // warp col  (0..1)
    const int g    = lane >> 2;      // group 0..7
    const int q    = lane & 3;       // quad  0..3

    const int rowBase = blockIdx.y * BM;
    const int colBase = blockIdx.x * BN;

    float acc[2][4][4];
#pragma unroll
    for (int mt = 0; mt < 2; mt++)
#pragma unroll
        for (int nt = 0; nt < 4; nt++)
#pragma unroll
            for (int r = 0; r < 4; r++) acc[mt][nt][r] = 0.0f;

    for (int k0 = 0; k0 < Kdim; k0 += BK) {
        // ---- fill A tile: As[m][k] (tf32) ----
        if (!ATrans) {
#pragma unroll
            for (int c = 0; c < 4; c++) {
                int idx = tid + 128 * c;            // 512 float4 loads
                int m  = idx >> 3;
                int kq = (idx & 7) * 4;
                float4 v = *(const float4*)(A + (long)(rowBase + m) * lda + k0 + kq);
                sm.ab.As[m][kq + 0] = f2tf32(v.x);
                sm.ab.As[m][kq + 1] = f2tf32(v.y);
                sm.ab.As[m][kq + 2] = f2tf32(v.z);
                sm.ab.As[m][kq + 3] = f2tf32(v.w);
            }
        } else {
#pragma unroll
            for (int c = 0; c < 4; c++) {
                int idx = tid + 128 * c;
                int k  = idx >> 4;
                int mq = (idx & 15) * 4;
                float4 v = *(const float4*)(A + (long)(k0 + k) * lda + rowBase + mq);
                sm.ab.As[mq + 0][k] = f2tf32(v.x);
                sm.ab.As[mq + 1][k] = f2tf32(v.y);
                sm.ab.As[mq + 2][k] = f2tf32(v.z);
                sm.ab.As[mq + 3][k] = f2tf32(v.w);
            }
        }
        // ---- fill B tile: Bs[n][k] ----
        if (!BTrans) {
#pragma unroll
            for (int c = 0; c < 4; c++) {
                int idx = tid + 128 * c;
                int n  = idx >> 3;
                int kq = (idx & 7) * 4;
                float4 v = *(const float4*)(B + (long)(colBase + n) * ldb + k0 + kq);
                sm.ab.Bs[n][kq + 0] = f2tf32(v.x);
                sm.ab.Bs[n][kq + 1] = f2tf32(v.y);
                sm.ab.Bs[n][kq + 2] = f2tf32(v.z);
                sm.ab.Bs[n][kq + 3] = f2tf32(v.w);
            }
        } else {
#pragma unroll
            for (int c = 0; c < 4; c++) {
                int idx = tid + 128 * c;
                int k  = idx >> 4;
                int nq = (idx & 15) * 4;
                float4 v = *(const float4*)(B + (long)(k0 + k) * ldb + colBase + nq);
                sm.ab.Bs[nq + 0][k] = f2tf32(v.x);
                sm.ab.Bs[nq + 1][k] = f2tf32(v.y);
                sm.ab.Bs[nq + 2][k] = f2tf32(v.z);
                sm.ab.Bs[nq + 3][k] = f2tf32(v.w);
            }
        }
        __syncthreads();

#pragma unroll
        for (int ks = 0; ks < 4; ks++) {
            unsigned a[2][4], b[4][2];
#pragma unroll
            for (int mt = 0; mt < 2; mt++) {
                int r0 = wm * 32 + mt * 16;
                a[mt][0] = sm.ab.As[r0 + g    ][ks * 8 + q];
                a[mt][1] = sm.ab.As[r0 + 8 + g][ks * 8 + q];
                a[mt][2] = sm.ab.As[r0 + g    ][ks * 8 + 4 + q];
                a[mt][3] = sm.ab.As[r0 + 8 + g][ks * 8 + 4 + q];
            }
#pragma unroll
            for (int nt = 0; nt < 4; nt++) {
                int c0 = wn * 32 + nt * 8;
                b[nt][0] = sm.ab.Bs[c0 + g][ks * 8 + q];
                b[nt][1] = sm.ab.Bs[c0 + g][ks * 8 + 4 + q];
            }
#pragma unroll
            for (int mt = 0; mt < 2; mt++)
#pragma unroll
                for (int nt = 0; nt < 4; nt++) {
                    asm volatile(
                        "mma.sync.aligned.m16n8k8.row.col.f32.tf32.tf32.f32 "
                        "{%0,%1,%2,%3},{%4,%5,%6,%7},{%8,%9},{%0,%1,%2,%3};"
                        : "+f"(acc[mt][nt][0]), "+f"(acc[mt][nt][1]),
                          "+f"(acc[mt][nt][2]), "+f"(acc[mt][nt][3])
                        : "r"(a[mt][0]), "r"(a[mt][1]), "r"(a[mt][2]), "r"(a[mt][3]),
                          "r"(b[nt][0]), "r"(b[nt][1]));
                }
        }
        __syncthreads();
    }

    if (EPI == 0) {
#pragma unroll
        for (int mt = 0; mt < 2; mt++)
#pragma unroll
            for (int nt = 0; nt < 4; nt++) {
                int row = rowBase + wm * 32 + mt * 16 + g;
                int col = colBase + wn * 32 + nt * 8 + 2 * q;
                *(float2*)(C + (long)row * ldc + col) =
                    make_float2(acc[mt][nt][0], acc[mt][nt][1]);
                *(float2*)(C + (long)(row + 8) * ldc + col) =
                    make_float2(acc[mt][nt][2], acc[mt][nt][3]);
            }
    } else if (EPI == 2) {
        float h = *hptr;
#pragma unroll
        for (int mt = 0; mt < 2; mt++)
#pragma unroll
            for (int nt = 0; nt < 4; nt++) {
                int row = rowBase + wm * 32 + mt * 16 + g;
                int col = colBase + wn * 32 + nt * 8 + 2 * q;
                float2 b0 = *(const float2*)(base + (long)row * ldc + col);
                float2 b1 = *(const float2*)(base + (long)(row + 8) * ldc + col);
                *(float2*)(C + (long)row * ldc + col) =
                    make_float2(b0.x + h * acc[mt][nt][0], b0.y + h * acc[mt][nt][1]);
                *(float2*)(C + (long)(row + 8) * ldc + col) =
                    make_float2(b1.x + h * acc[mt][nt][2], b1.y + h * acc[mt][nt][3]);
            }
    } else {
        // EPI 1: stage to smem, then quat-normalize + feature expansion
#pragma unroll
        for (int mt = 0; mt < 2; mt++)
#pragma unroll
            for (int nt = 0; nt < 4; nt++) {
                int lr = wm * 32 + mt * 16 + g;
                int lc = wn * 32 + nt * 8 + 2 * q;
                sm.Cs[lr][lc]     = acc[mt][nt][0];
                sm.Cs[lr][lc + 1] = acc[mt][nt][1];
                sm.Cs[lr + 8][lc]     = acc[mt][nt][2];
                sm.Cs[lr + 8][lc + 1] = acc[mt][nt][3];
            }
        __syncthreads();
#pragma unroll
        for (int c = 0; c < 8; c++) {
            int qi = tid + 128 * c;       // 1024 quats per CTA
            int lr = qi >> 4;
            int hq = qi & 15;
            float4 bb = *(const float4*)(aux + colBase + hq * 4);
            float w = sm.Cs[lr][hq * 4 + 0] + bb.x;
            float x = sm.Cs[lr][hq * 4 + 1] + bb.y;
            float y = sm.Cs[lr][hq * 4 + 2] + bb.z;
            float zz = sm.Cs[lr][hq * 4 + 3] + bb.w;
            float inv = 1.0f / (sqrtf(w * w + x * x + y * y + zz * zz) + 1e-8f);
            w *= inv; x *= inv; y *= inv; zz *= inv;
            float* o = C + (long)(rowBase + lr) * KF + ((colBase >> 2) + hq) * 10;
            o[0] = w * w;
            o[1] = fmult * w * x;
            o[2] = fmult * w * y;
            o[3] = fmult * w * zz;
            o[4] = x * x;
            o[5] = fmult * x * y;
            o[6] = fmult * x * zz;
            o[7] = y * y;
            o[8] = fmult * y * zz;
            o[9] = zz * zz;
        }
    }
}

// ---------------------------------------------------------------------------
// Row softmax over M=512 (in place). Logits = S / 1024 (mean_h / sqrt(D)).
// ---------------------------------------------------------------------------
__global__ void __launch_bounds__(256)
softmax_k(float* __restrict__ S)
{
    const float SC = 1.0f / 1024.0f;
    float* p = S + (size_t)blockIdx.x * MM;
    int t = threadIdx.x;
    float a = p[t] * SC;
    float b = p[t + 256] * SC;

    __shared__ float red[8];
    float m = fmaxf(a, b);
#pragma unroll
    for (int o = 16; o > 0; o >>= 1) m = fmaxf(m, __shfl_xor_sync(0xffffffffu, m, o));
    if ((t & 31) == 0) red[t >> 5] = m;
    __syncthreads();
    if (t < 32) {
        float v = (t < 8) ? red[t] : -3.0e38f;
#pragma unroll
        for (int o = 4; o > 0; o >>= 1) v = fmaxf(v, __shfl_xor_sync(0xffffffffu, v, o));
        if (t == 0) red[0] = v;
    }
    __syncthreads();
    float Mx = red[0];
    __syncthreads();

    float e1 = __expf(a - Mx);
    float e2 = __expf(b - Mx);
    float s = e1 + e2;
#pragma unroll
    for (int o = 16; o > 0; o >>= 1) s += __shfl_xor_sync(0xffffffffu, s, o);
    if ((t & 31) == 0) red[t >> 5] = s;
    __syncthreads();
    if (t < 32) {
        float v = (t < 8) ? red[t] : 0.0f;
#pragma unroll
        for (int o = 4; o > 0; o >>= 1) v += __shfl_xor_sync(0xffffffffu, v, o);
        if (t == 0) red[0] = v;
    }
    __syncthreads();
    float inv = 1.0f / red[0];
    p[t] = e1 * inv;
    p[t + 256] = e2 * inv;
}

// ---------------------------------------------------------------------------
extern "C" void kernel_launch(void* const* d_in, const int* in_sizes, int n_in,
                              void* d_out, int out_size)
{
    (void)in_sizes; (void)n_in; (void)out_size;

    const float* vision = (const float*)d_in[0];  // (B,N,D)
    const float* text   = (const float*)d_in[1];  // (B,M,D)
    const float* Wv     = (const float*)d_in[2];  // (D,D)
    const float* bv     = (const float*)d_in[3];  // (D,)
    const float* Wt     = (const float*)d_in[4];  // (D,D)
    const float* bt     = (const float*)d_in[5];  // (D,)
    const float* hp     = (const float*)d_in[6];  // scalar

    float* outv = (float*)d_out;
    float* outt = outv + (size_t)BB * NN * DD;

    float* scr = nullptr;
    cudaGetSymbolAddress((void**)&scr, g_scratch);
    float* Fv = scr + OFF_FV;
    float* Ft = scr + OFF_FT;
    float* S  = scr + OFF_S;

    // 1) Projections: quat-normalize + feature expansion fused into epilogue.
    //    "C" arg receives the feature matrix (row-major, KF=640 wide).
    {
        dim3 grid(DD / BN, RTOT / BM, 1);
        tgemm<false, false, 1><<<grid, 128>>>(vision, Wv, Fv, DD, DD, DD, 0,
                                              0, 0, 0, bv, 0, nullptr, 1.0f);
        tgemm<false, false, 1><<<grid, 128>>>(text, Wt, Ft, DD, DD, DD, 0,
                                              0, 0, 0, bt, 0, nullptr, 2.0f);
    }

    // 2) Score GEMM: S[b,n,m] = sum_k Fv[b,n,k] * Ft[b,m,k]
    {
        dim3 grid(MM / BN, NN / BM, BB);
        tgemm<false, false, 0><<<grid, 128>>>(Fv, Ft, S, KF, KF, KF, MM,
                                              (long)NN * KF, (long)MM * KF,
                                              (long)NN * MM, nullptr, 0, nullptr, 0.0f);
    }

    // 3) Softmax over m (in place)
    softmax_k<<<BB * NN, 256>>>(S);

    // 4) out_vision = vision + h * (A @ text)
    {
        dim3 grid(DD / BN, NN / BM, BB);
        tgemm<false, true, 2><<<grid, 128>>>(S, text, outv, MM, MM, DD, DD,
                                             (long)NN * MM, (long)MM * DD,
                                             (long)NN * DD, vision,
                                             (long)NN * DD, hp, 0.0f);
    }
    // 5) out_text = text + h * (A^T @ vision)
    {
        dim3 grid(DD / BN, MM / BM, BB);
        tgemm<true, true, 2><<<grid, 128>>>(S, vision, outt, NN, MM, DD, DD,
                                            (long)NN * MM, (long)NN * DD,
                                            (long)MM * DD, text,
                                            (long)MM * DD, hp, 0.0f);
    }
}

// round 3
// speedup vs baseline: 2.2534x; 2.1002x over previous
#include <cuda_runtime.h>
#include <cstdint>
#include <math.h>

// Problem shapes (fixed by dataset)
#define BB 2
#define NN 512
#define MM 512
#define DD 256
#define KF 640            // heads * 10 symmetric features
#define RTOT (BB*NN)      // 1024 projection rows

// Scratch
#define OFF_FV 0
#define OFF_FT (OFF_FV + (size_t)RTOT*KF)
#define OFF_S  (OFF_FT + (size_t)RTOT*KF)
#define SCRATCH_FLOATS (OFF_S + (size_t)BB*NN*MM)

__device__ __align__(16) float g_scratch[SCRATCH_FLOATS];

__device__ __forceinline__ void cp16(uint32_t dst, const void* src) {
    asm volatile("cp.async.ca.shared.global [%0], [%1], 16;\n" :: "r"(dst), "l"(src));
}
__device__ __forceinline__ void cp_commit() {
    asm volatile("cp.async.commit_group;\n");
}
template <int N> __device__ __forceinline__ void cp_wait() {
    asm volatile("cp.async.wait_group %0;\n" :: "n"(N));
}

// ---------------------------------------------------------------------------
// Tensor-core GEMM: C[i,j] = sum_k A(i,k) * B(j,k)   (tf32 mma, fp32 accum,
// fp32 operands truncated to tf32 by the MMA hardware — no cvt needed).
//   Lay==0: operand is k-contiguous in gmem  (A(i,k)=A[i*lda+k])
//           -> smem tile stored [m][pitch36]
//   Lay==1: operand is m-contiguous in gmem  (A(i,k)=A[k*lda+i])
//           -> smem tile stored [k][pitch72]
// EPI: 0 plain store; 1 quat-normalize (+bias aux) + feature expansion;
//      2 residual C = aux + (*hptr)*acc
// CTA 64x64, BK=32, 128 thr (4 warps, 2x2 warp grid, 32x32/warp),
// 2-stage cp.async double buffer.
// ---------------------------------------------------------------------------
#define TILEF 2304   // floats per tile (64*36 == 32*72)

template <int ALay, int BLay, int EPI>
__global__ void __launch_bounds__(128)
tgemm(const float* __restrict__ A, const float* __restrict__ B,
      float* __restrict__ C, int Kdim, int lda, int ldb, int ldc,
      long sA, long sB, long sC,
      const float* __restrict__ aux, long sAux,
      const float* __restrict__ hptr, float fmult)
{
    __shared__ __align__(16) union {
        float ab[2][2][TILEF];     // [stage][0=A,1=B]
        float Cs[64][68];
    } sm;

    const int z = blockIdx.z;
    A += (long)z * sA;
    B += (long)z * sB;
    C += (long)z * sC;
    const float* rbase = aux;
    if (EPI == 2) rbase += (long)z * sAux;

    const int tid  = threadIdx.x;
    const int lane = tid & 31;
    const int wid  = tid >> 5;
    const int wm   = wid >> 1;
    const int wn   = wid & 1;
    const int g    = lane >> 2;
    const int q    = lane & 3;

    const int rowBase = blockIdx.y * 64;
    const int colBase = blockIdx.x * 64;

    float acc[2][4][4];
#pragma unroll
    for (int mt = 0; mt < 2; mt++)
#pragma unroll
        for (int nt = 0; nt < 4; nt++)
#pragma unroll
            for (int r = 0; r < 4; r++) acc[mt][nt][r] = 0.0f;

    // ---- async tile fills ----
    auto fillA = [&](int st, int k0) {
        uint32_t base = (uint32_t)__cvta_generic_to_shared(&sm.ab[st][0][0]);
        if (ALay == 0) {
#pragma unroll
            for (int j = 0; j < 4; j++) {
                int idx = tid + 128 * j;
                int r = idx >> 3, ch = idx & 7;
                cp16(base + (r * 36 + ch * 4) * 4,
                     A + (long)(rowBase + r) * lda + k0 + ch * 4);
            }
        } else {
#pragma unroll
            for (int j = 0; j < 4; j++) {
                int idx = tid + 128 * j;
                int k = idx >> 4, ch = idx & 15;
                cp16(base + (k * 72 + ch * 4) * 4,
                     A + (long)(k0 + k) * lda + rowBase + ch * 4);
            }
        }
    };
    auto fillB = [&](int st, int k0) {
        uint32_t base = (uint32_t)__cvta_generic_to_shared(&sm.ab[st][1][0]);
        if (BLay == 0) {
#pragma unroll
            for (int j = 0; j < 4; j++) {
                int idx = tid + 128 * j;
                int r = idx >> 3, ch = idx & 7;
                cp16(base + (r * 36 + ch * 4) * 4,
                     B + (long)(colBase + r) * ldb + k0 + ch * 4);
            }
        } else {
#pragma unroll
            for (int j = 0; j < 4; j++) {
                int idx = tid + 128 * j;
                int k = idx >> 4, ch = idx & 15;
                cp16(base + (k * 72 + ch * 4) * 4,
                     B + (long)(k0 + k) * ldb + colBase + ch * 4);
            }
        }
    };

    const int niter = Kdim >> 5;
    fillA(0, 0);
    fillB(0, 0);
    cp_commit();

    for (int i = 0; i < niter; i++) {
        const int cur = i & 1;
        if (i + 1 < niter) {
            fillA(cur ^ 1, (i + 1) * 32);
            fillB(cur ^ 1, (i + 1) * 32);
            cp_commit();
            cp_wait<1>();
        } else {
            cp_wait<0>();
        }
        __syncthreads();

        const unsigned* fA = (const unsigned*)&sm.ab[cur][0][0];
        const unsigned* fB = (const unsigned*)&sm.ab[cur][1][0];

#pragma unroll
        for (int ks = 0; ks < 4; ks++) {
            unsigned a[2][4], b[4][2];
#pragma unroll
            for (int mt = 0; mt < 2; mt++) {
                int r0 = wm * 32 + mt * 16;
                if (ALay == 0) {
                    a[mt][0] = fA[(r0 + g)     * 36 + ks * 8 + q];
                    a[mt][1] = fA[(r0 + 8 + g) * 36 + ks * 8 + q];
                    a[mt][2] = fA[(r0 + g)     * 36 + ks * 8 + 4 + q];
                    a[mt][3] = fA[(r0 + 8 + g) * 36 + ks * 8 + 4 + q];
                } else {
                    a[mt][0] = fA[(ks * 8 + q)     * 72 + r0 + g];
                    a[mt][1] = fA[(ks * 8 + q)     * 72 + r0 + 8 + g];
                    a[mt][2] = fA[(ks * 8 + 4 + q) * 72 + r0 + g];
                    a[mt][3] = fA[(ks * 8 + 4 + q) * 72 + r0 + 8 + g];
                }
            }
#pragma unroll
            for (int nt = 0; nt < 4; nt++) {
                int c0 = wn * 32 + nt * 8;
                if (BLay == 0) {
                    b[nt][0] = fB[(c0 + g) * 36 + ks * 8 + q];
                    b[nt][1] = fB[(c0 + g) * 36 + ks * 8 + 4 + q];
                } else {
                    b[nt][0] = fB[(ks * 8 + q)     * 72 + c0 + g];
                    b[nt][1] = fB[(ks * 8 + 4 + q) * 72 + c0 + g];
                }
            }
#pragma unroll
            for (int mt = 0; mt < 2; mt++)
#pragma unroll
                for (int nt = 0; nt < 4; nt++) {
                    asm volatile(
                        "mma.sync.aligned.m16n8k8.row.col.f32.tf32.tf32.f32 "
                        "{%0,%1,%2,%3},{%4,%5,%6,%7},{%8,%9},{%0,%1,%2,%3};"
                        : "+f"(acc[mt][nt][0]), "+f"(acc[mt][nt][1]),
                          "+f"(acc[mt][nt][2]), "+f"(acc[mt][nt][3])
                        : "r"(a[mt][0]), "r"(a[mt][1]), "r"(a[mt][2]), "r"(a[mt][3]),
                          "r"(b[nt][0]), "r"(b[nt][1]));
                }
        }
        __syncthreads();
    }

    if (EPI == 0) {
#pragma unroll
        for (int mt = 0; mt < 2; mt++)
#pragma unroll
            for (int nt = 0; nt < 4; nt++) {
                int row = rowBase + wm * 32 + mt * 16 + g;
                int col = colBase + wn * 32 + nt * 8 + 2 * q;
                *(float2*)(C + (long)row * ldc + col) =
                    make_float2(acc[mt][nt][0], acc[mt][nt][1]);
                *(float2*)(C + (long)(row + 8) * ldc + col) =
                    make_float2(acc[mt][nt][2], acc[mt][nt][3]);
            }
    } else if (EPI == 2) {
        float h = __ldg(hptr);
#pragma unroll
        for (int mt = 0; mt < 2; mt++)
#pragma unroll
            for (int nt = 0; nt < 4; nt++) {
                int row = rowBase + wm * 32 + mt * 16 + g;
                int col = colBase + wn * 32 + nt * 8 + 2 * q;
                float2 b0 = *(const float2*)(rbase + (long)row * ldc + col);
                float2 b1 = *(const float2*)(rbase + (long)(row + 8) * ldc + col);
                *(float2*)(C + (long)row * ldc + col) =
                    make_float2(b0.x + h * acc[mt][nt][0], b0.y + h * acc[mt][nt][1]);
                *(float2*)(C + (long)(row + 8) * ldc + col) =
                    make_float2(b1.x + h * acc[mt][nt][2], b1.y + h * acc[mt][nt][3]);
            }
    } else {
        // EPI 1: stage to smem, then quat-normalize + 10-feature expansion
#pragma unroll
        for (int mt = 0; mt < 2; mt++)
#pragma unroll
            for (int nt = 0; nt < 4; nt++) {
                int lr = wm * 32 + mt * 16 + g;
                int lc = wn * 32 + nt * 8 + 2 * q;
                sm.Cs[lr][lc]     = acc[mt][nt][0];
                sm.Cs[lr][lc + 1] = acc[mt][nt][1];
                sm.Cs[lr + 8][lc]     = acc[mt][nt][2];
                sm.Cs[lr + 8][lc + 1] = acc[mt][nt][3];
            }
        __syncthreads();
#pragma unroll
        for (int c = 0; c < 8; c++) {
            int qi = tid + 128 * c;       // 1024 quats per CTA
            int lr = qi >> 4;
            int hq = qi & 15;
            float4 bb = *(const float4*)(aux + colBase + hq * 4);
            float w  = sm.Cs[lr][hq * 4 + 0] + bb.x;
            float x  = sm.Cs[lr][hq * 4 + 1] + bb.y;
            float y  = sm.Cs[lr][hq * 4 + 2] + bb.z;
            float zz = sm.Cs[lr][hq * 4 + 3] + bb.w;
            float inv = 1.0f / (sqrtf(w * w + x * x + y * y + zz * zz) + 1e-8f);
            w *= inv; x *= inv; y *= inv; zz *= inv;
            float* o = C + (long)(rowBase + lr) * KF + ((colBase >> 2) + hq) * 10;
            o[0] = w * w;
            o[1] = fmult * w * x;
            o[2] = fmult * w * y;
            o[3] = fmult * w * zz;
            o[4] = x * x;
            o[5] = fmult * x * y;
            o[6] = fmult * x * zz;
            o[7] = y * y;
            o[8] = fmult * y * zz;
            o[9] = zz * zz;
        }
    }
}

// ---------------------------------------------------------------------------
// Warp-per-row softmax over M=512 (in place). Logits = S / 1024.
// grid = RTOT/8 CTAs, 256 threads (8 warps -> 8 rows).
// ---------------------------------------------------------------------------
__global__ void __launch_bounds__(256)
softmax_k(float* __restrict__ S)
{
    const float SC = 1.0f / 1024.0f;
    const int warp = threadIdx.x >> 5;
    const int lane = threadIdx.x & 31;
    float* p = S + ((size_t)blockIdx.x * 8 + warp) * MM;

    float4 v[4];
    float mx = -3.0e38f;
#pragma unroll
    for (int j = 0; j < 4; j++) {
        v[j] = *(const float4*)(p + lane * 4 + j * 128);
        v[j].x *= SC; v[j].y *= SC; v[j].z *= SC; v[j].w *= SC;
        mx = fmaxf(mx, fmaxf(fmaxf(v[j].x, v[j].y), fmaxf(v[j].z, v[j].w)));
    }
#pragma unroll
    for (int o = 16; o > 0; o >>= 1) mx = fmaxf(mx, __shfl_xor_sync(0xffffffffu, mx, o));

    float s = 0.0f;
#pragma unroll
    for (int j = 0; j < 4; j++) {
        v[j].x = __expf(v[j].x - mx);
        v[j].y = __expf(v[j].y - mx);
        v[j].z = __expf(v[j].z - mx);
        v[j].w = __expf(v[j].w - mx);
        s += v[j].x + v[j].y + v[j].z + v[j].w;
    }
#pragma unroll
    for (int o = 16; o > 0; o >>= 1) s += __shfl_xor_sync(0xffffffffu, s, o);
    float inv = 1.0f / s;
#pragma unroll
    for (int j = 0; j < 4; j++) {
        v[j].x *= inv; v[j].y *= inv; v[j].z *= inv; v[j].w *= inv;
        *(float4*)(p + lane * 4 + j * 128) = v[j];
    }
}

// ---------------------------------------------------------------------------
extern "C" void kernel_launch(void* const* d_in, const int* in_sizes, int n_in,
                              void* d_out, int out_size)
{
    (void)in_sizes; (void)n_in; (void)out_size;

    const float* vision = (const float*)d_in[0];  // (B,N,D)
    const float* text   = (const float*)d_in[1];  // (B,M,D)
    const float* Wv     = (const float*)d_in[2];  // (D,D)
    const float* bv     = (const float*)d_in[3];  // (D,)
    const float* Wt     = (const float*)d_in[4];  // (D,D)
    const float* bt     = (const float*)d_in[5];  // (D,)
    const float* hp     = (const float*)d_in[6];  // scalar

    float* outv = (float*)d_out;
    float* outt = outv + (size_t)BB * NN * DD;

    float* scr = nullptr;
    cudaGetSymbolAddress((void**)&scr, g_scratch);
    float* Fv = scr + OFF_FV;
    float* Ft = scr + OFF_FT;
    float* S  = scr + OFF_S;

    // 1) Projections: quat-normalize + feature expansion fused into epilogue.
    {
        dim3 grid(DD / 64, RTOT / 64, 1);
        tgemm<0, 0, 1><<<grid, 128>>>(vision, Wv, Fv, DD, DD, DD, 0,
                                      0, 0, 0, bv, 0, nullptr, 1.0f);
        tgemm<0, 0, 1><<<grid, 128>>>(text, Wt, Ft, DD, DD, DD, 0,
                                      0, 0, 0, bt, 0, nullptr, 2.0f);
    }

    // 2) Score GEMM: S[b,n,m] = sum_k Fv[b,n,k] * Ft[b,m,k]
    {
        dim3 grid(MM / 64, NN / 64, BB);
        tgemm<0, 0, 0><<<grid, 128>>>(Fv, Ft, S, KF, KF, KF, MM,
                                      (long)NN * KF, (long)MM * KF,
                                      (long)NN * MM, nullptr, 0, nullptr, 0.0f);
    }

    // 3) Softmax over m (in place)
    softmax_k<<<RTOT / 8, 256>>>(S);

    // 4) out_vision = vision + h * (A @ text)
    {
        dim3 grid(DD / 64, NN / 64, BB);
        tgemm<0, 1, 2><<<grid, 128>>>(S, text, outv, MM, MM, DD, DD,
                                      (long)NN * MM, (long)MM * DD,
                                      (long)NN * DD, vision,
                                      (long)NN * DD, hp, 0.0f);
    }
    // 5) out_text = text + h * (A^T @ vision)
    {
        dim3 grid(DD / 64, MM / 64, BB);
        tgemm<1, 1, 2><<<grid, 128>>>(S, vision, outt, NN, MM, DD, DD,
                                      (long)NN * MM, (long)NN * DD,
                                      (long)MM * DD, text,
                                      (long)MM * DD, hp, 0.0f);
    }
}

// round 4
// speedup vs baseline: 3.1183x; 1.3838x over previous
#include <cuda_runtime.h>
#include <cstdint>
#include <math.h>

// Problem shapes (fixed by dataset)
#define BB 2
#define NN 512
#define MM 512
#define DD 256
#define KF 640            // heads * 10 symmetric features
#define RTOT (BB*NN)      // 1024 projection rows

// Scratch
#define OFF_FV 0
#define OFF_FT (OFF_FV + (size_t)RTOT*KF)
#define OFF_E  (OFF_FT + (size_t)RTOT*KF)
#define OFF_RS (OFF_E + (size_t)BB*NN*MM)
#define OFF_VS (OFF_RS + (size_t)RTOT)
#define SCRATCH_FLOATS (OFF_VS + (size_t)RTOT*DD)

__device__ __align__(16) float g_scratch[SCRATCH_FLOATS];

__device__ __forceinline__ void cp16(uint32_t dst, const void* src) {
    asm volatile("cp.async.ca.shared.global [%0], [%1], 16;\n" :: "r"(dst), "l"(src));
}
__device__ __forceinline__ void cp_commit() {
    asm volatile("cp.async.commit_group;\n");
}
template <int N> __device__ __forceinline__ void cp_wait() {
    asm volatile("cp.async.wait_group %0;\n" :: "n"(N));
}

#define TILEF 2304   // floats per tile (64*36 == 32*72)
struct SmemT { float ab[2][2][TILEF]; };   // [stage][0=A,1=B]

// ---------------------------------------------------------------------------
// Shared tf32 MMA mainloop. C tile 64x64, BK=32, 128 threads (2x2 warps,
// 32x32 per warp), 2-stage cp.async double buffer.
//   Lay==0: operand k-contiguous (X(i,k)=X[i*ld+k]) -> smem [i][pitch 36]
//   Lay==1: operand i-contiguous (X(i,k)=X[k*ld+i]) -> smem [k][pitch 72]
// ---------------------------------------------------------------------------
template <int ALay, int BLay>
__device__ __forceinline__ void gemm_main(
    const float* __restrict__ A, const float* __restrict__ B,
    int Kdim, int lda, int ldb, int rowBase, int colBase,
    SmemT& sm, float acc[2][4][4])
{
    const int tid  = threadIdx.x;
    const int lane = tid & 31;
    const int wid  = tid >> 5;
    const int wm   = wid >> 1;
    const int wn   = wid & 1;
    const int g    = lane >> 2;
    const int q    = lane & 3;

#pragma unroll
    for (int mt = 0; mt < 2; mt++)
#pragma unroll
        for (int nt = 0; nt < 4; nt++)
#pragma unroll
            for (int r = 0; r < 4; r++) acc[mt][nt][r] = 0.0f;

    auto fillA = [&](int st, int k0) {
        uint32_t base = (uint32_t)__cvta_generic_to_shared(&sm.ab[st][0][0]);
        if (ALay == 0) {
#pragma unroll
            for (int j = 0; j < 4; j++) {
                int idx = tid + 128 * j;
                int r = idx >> 3, ch = idx & 7;
                cp16(base + (r * 36 + ch * 4) * 4,
                     A + (long)(rowBase + r) * lda + k0 + ch * 4);
            }
        } else {
#pragma unroll
            for (int j = 0; j < 4; j++) {
                int idx = tid + 128 * j;
                int k = idx >> 4, ch = idx & 15;
                cp16(base + (k * 72 + ch * 4) * 4,
                     A + (long)(k0 + k) * lda + rowBase + ch * 4);
            }
        }
    };
    auto fillB = [&](int st, int k0) {
        uint32_t base = (uint32_t)__cvta_generic_to_shared(&sm.ab[st][1][0]);
        if (BLay == 0) {
#pragma unroll
            for (int j = 0; j < 4; j++) {
                int idx = tid + 128 * j;
                int r = idx >> 3, ch = idx & 7;
                cp16(base + (r * 36 + ch * 4) * 4,
                     B + (long)(colBase + r) * ldb + k0 + ch * 4);
            }
        } else {
#pragma unroll
            for (int j = 0; j < 4; j++) {
                int idx = tid + 128 * j;
                int k = idx >> 4, ch = idx & 15;
                cp16(base + (k * 72 + ch * 4) * 4,
                     B + (long)(k0 + k) * ldb + colBase + ch * 4);
            }
        }
    };

    const int niter = Kdim >> 5;
    fillA(0, 0);
    fillB(0, 0);
    cp_commit();

    for (int i = 0; i < niter; i++) {
        const int cur = i & 1;
        if (i + 1 < niter) {
            fillA(cur ^ 1, (i + 1) * 32);
            fillB(cur ^ 1, (i + 1) * 32);
            cp_commit();
            cp_wait<1>();
        } else {
            cp_wait<0>();
        }
        __syncthreads();

        const unsigned* fA = (const unsigned*)&sm.ab[cur][0][0];
        const unsigned* fB = (const unsigned*)&sm.ab[cur][1][0];

#pragma unroll
        for (int ks = 0; ks < 4; ks++) {
            unsigned a[2][4], b[4][2];
#pragma unroll
            for (int mt = 0; mt < 2; mt++) {
                int r0 = wm * 32 + mt * 16;
                if (ALay == 0) {
                    a[mt][0] = fA[(r0 + g)     * 36 + ks * 8 + q];
                    a[mt][1] = fA[(r0 + 8 + g) * 36 + ks * 8 + q];
                    a[mt][2] = fA[(r0 + g)     * 36 + ks * 8 + 4 + q];
                    a[mt][3] = fA[(r0 + 8 + g) * 36 + ks * 8 + 4 + q];
                } else {
                    a[mt][0] = fA[(ks * 8 + q)     * 72 + r0 + g];
                    a[mt][1] = fA[(ks * 8 + q)     * 72 + r0 + 8 + g];
                    a[mt][2] = fA[(ks * 8 + 4 + q) * 72 + r0 + g];
                    a[mt][3] = fA[(ks * 8 + 4 + q) * 72 + r0 + 8 + g];
                }
            }
#pragma unroll
            for (int nt = 0; nt < 4; nt++) {
                int c0 = wn * 32 + nt * 8;
                if (BLay == 0) {
                    b[nt][0] = fB[(c0 + g) * 36 + ks * 8 + q];
                    b[nt][1] = fB[(c0 + g) * 36 + ks * 8 + 4 + q];
                } else {
                    b[nt][0] = fB[(ks * 8 + q)     * 72 + c0 + g];
                    b[nt][1] = fB[(ks * 8 + 4 + q) * 72 + c0 + g];
                }
            }
#pragma unroll
            for (int mt = 0; mt < 2; mt++)
#pragma unroll
                for (int nt = 0; nt < 4; nt++) {
                    asm volatile(
                        "mma.sync.aligned.m16n8k8.row.col.f32.tf32.tf32.f32 "
                        "{%0,%1,%2,%3},{%4,%5,%6,%7},{%8,%9},{%0,%1,%2,%3};"
                        : "+f"(acc[mt][nt][0]), "+f"(acc[mt][nt][1]),
                          "+f"(acc[mt][nt][2]), "+f"(acc[mt][nt][3])
                        : "r"(a[mt][0]), "r"(a[mt][1]), "r"(a[mt][2]), "r"(a[mt][3]),
                          "r"(b[nt][0]), "r"(b[nt][1]));
                }
        }
        __syncthreads();
    }
}

// ---------------------------------------------------------------------------
// 1) Combined projection: z=0 vision/Wv/bv (fmult 1), z=1 text/Wt/bt (fmult 2).
//    Epilogue: +bias, quat-normalize, 10-feature expansion into Fout (KF wide).
//    Linear CTA ids 0..3 also zero the rowsum array for the score pass.
// ---------------------------------------------------------------------------
__global__ void __launch_bounds__(128)
proj_k(const float* __restrict__ vis, const float* __restrict__ txt,
       const float* __restrict__ Wv, const float* __restrict__ Wt,
       const float* __restrict__ bv, const float* __restrict__ bt,
       float* __restrict__ Fv, float* __restrict__ Ft,
       float* __restrict__ rowsum)
{
    __shared__ __align__(16) union { SmemT t; float Cs[64][68]; } sm;

    const int z = blockIdx.z;
    const int linear = blockIdx.x + blockIdx.y * gridDim.x +
                       z * gridDim.x * gridDim.y;
    if (linear < 4) {
        rowsum[linear * 256 + threadIdx.x] = 0.0f;
        rowsum[linear * 256 + 128 + threadIdx.x] = 0.0f;
    }

    const float* A   = z ? txt : vis;
    const float* W   = z ? Wt : Wv;
    const float* bia = z ? bt : bv;
    float* Fout      = z ? Ft : Fv;
    const float fmult = z ? 2.0f : 1.0f;

    const int rowBase = blockIdx.y * 64;
    const int colBase = blockIdx.x * 64;
    const int tid = threadIdx.x;
    const int lane = tid & 31, wid = tid >> 5;
    const int wm = wid >> 1, wn = wid & 1, g = lane >> 2, q = lane & 3;

    float acc[2][4][4];
    gemm_main<0, 0>(A, W, DD, DD, DD, rowBase, colBase, sm.t, acc);

#pragma unroll
    for (int mt = 0; mt < 2; mt++)
#pragma unroll
        for (int nt = 0; nt < 4; nt++) {
            int lr = wm * 32 + mt * 16 + g;
            int lc = wn * 32 + nt * 8 + 2 * q;
            sm.Cs[lr][lc]         = acc[mt][nt][0];
            sm.Cs[lr][lc + 1]     = acc[mt][nt][1];
            sm.Cs[lr + 8][lc]     = acc[mt][nt][2];
            sm.Cs[lr + 8][lc + 1] = acc[mt][nt][3];
        }
    __syncthreads();
#pragma unroll
    for (int c = 0; c < 8; c++) {
        int qi = tid + 128 * c;       // 1024 quats per CTA
        int lr = qi >> 4;
        int hq = qi & 15;
        float4 bb = *(const float4*)(bia + colBase + hq * 4);
        float w  = sm.Cs[lr][hq * 4 + 0] + bb.x;
        float x  = sm.Cs[lr][hq * 4 + 1] + bb.y;
        float y  = sm.Cs[lr][hq * 4 + 2] + bb.z;
        float zz = sm.Cs[lr][hq * 4 + 3] + bb.w;
        float inv = 1.0f / (sqrtf(w * w + x * x + y * y + zz * zz) + 1e-8f);
        w *= inv; x *= inv; y *= inv; zz *= inv;
        float* o = Fout + (long)(rowBase + lr) * KF + ((colBase >> 2) + hq) * 10;
        o[0] = w * w;
        o[1] = fmult * w * x;
        o[2] = fmult * w * y;
        o[3] = fmult * w * zz;
        o[4] = x * x;
        o[5] = fmult * x * y;
        o[6] = fmult * x * zz;
        o[7] = y * y;
        o[8] = fmult * y * zz;
        o[9] = zz * zz;
    }
}

// ---------------------------------------------------------------------------
// 2) Score GEMM + exp epilogue + rowsum atomics.
//    E[b,n,m] = exp( (Fv.Ft)/1024 ), rowsum[b*NN+n] += row partials.
//    (Logits are in [0, 1/16] so max-subtraction is unnecessary.)
// ---------------------------------------------------------------------------
__global__ void __launch_bounds__(128)
score_k(const float* __restrict__ Fv, const float* __restrict__ Ft,
        float* __restrict__ E, float* __restrict__ rowsum)
{
    __shared__ __align__(16) SmemT sm;
    const int z = blockIdx.z;
    const float* A = Fv + (long)z * NN * KF;
    const float* B = Ft + (long)z * MM * KF;
    float* C = E + (long)z * NN * MM;

    const int rowBase = blockIdx.y * 64;
    const int colBase = blockIdx.x * 64;
    const int tid = threadIdx.x;
    const int lane = tid & 31, wid = tid >> 5;
    const int wm = wid >> 1, wn = wid & 1, g = lane >> 2, q = lane & 3;

    float acc[2][4][4];
    gemm_main<0, 0>(A, B, KF, KF, KF, rowBase, colBase, sm, acc);

    const float SC = 1.0f / 1024.0f;
    float rsum[2][2] = {{0.f, 0.f}, {0.f, 0.f}};
#pragma unroll
    for (int mt = 0; mt < 2; mt++)
#pragma unroll
        for (int nt = 0; nt < 4; nt++) {
            int row = rowBase + wm * 32 + mt * 16 + g;
            int col = colBase + wn * 32 + nt * 8 + 2 * q;
            float e0 = __expf(acc[mt][nt][0] * SC);
            float e1 = __expf(acc[mt][nt][1] * SC);
            float e2 = __expf(acc[mt][nt][2] * SC);
            float e3 = __expf(acc[mt][nt][3] * SC);
            *(float2*)(C + (long)row * MM + col)       = make_float2(e0, e1);
            *(float2*)(C + (long)(row + 8) * MM + col) = make_float2(e2, e3);
            rsum[mt][0] += e0 + e1;
            rsum[mt][1] += e2 + e3;
        }
    // quad-reduce (lanes sharing g hold the same rows)
#pragma unroll
    for (int mt = 0; mt < 2; mt++)
#pragma unroll
        for (int hh = 0; hh < 2; hh++) {
            float v = rsum[mt][hh];
            v += __shfl_xor_sync(0xffffffffu, v, 1);
            v += __shfl_xor_sync(0xffffffffu, v, 2);
            if (q == 0) {
                int row = rowBase + wm * 32 + mt * 16 + hh * 8 + g;
                atomicAdd(&rowsum[z * NN + row], v);
            }
        }
}

// ---------------------------------------------------------------------------
// 3) vscale: v'[r,d] = vision[r,d] / rowsum[r]   (r = global projection row)
// ---------------------------------------------------------------------------
__global__ void __launch_bounds__(128)
vscale_k(const float4* __restrict__ vis, const float* __restrict__ rowsum,
         float4* __restrict__ vs)
{
    int idx = blockIdx.x * 128 + threadIdx.x;   // RTOT*DD/4 = 65536
    int row = idx >> 6;                          // DD/4 = 64 float4 per row
    float inv = 1.0f / rowsum[row];
    float4 v = vis[idx];
    v.x *= inv; v.y *= inv; v.z *= inv; v.w *= inv;
    vs[idx] = v;
}

// ---------------------------------------------------------------------------
// 4) Combined output GEMM. z=(sel<<1)|b.
//    sel=0: outv[b] = vision + (h/rs[row]) * E[b] @ text[b]        (A lay0, B lay1)
//    sel=1: outt[b] = text   +  h          * E[b]^T @ v'[b]        (A lay1, B lay1)
// ---------------------------------------------------------------------------
__global__ void __launch_bounds__(128)
out_k(const float* __restrict__ E, const float* __restrict__ vis,
      const float* __restrict__ txt, const float* __restrict__ vsc,
      const float* __restrict__ rowsum, const float* __restrict__ hptr,
      float* __restrict__ outv, float* __restrict__ outt)
{
    __shared__ __align__(16) SmemT sm;
    const int zz = blockIdx.z;
    const int b = zz & 1;
    const int sel = zz >> 1;

    const int rowBase = blockIdx.y * 64;
    const int colBase = blockIdx.x * 64;
    const int tid = threadIdx.x;
    const int lane = tid & 31, wid = tid >> 5;
    const int wm = wid >> 1, wn = wid & 1, g = lane >> 2, q = lane & 3;

    const float* A = E + (long)b * NN * MM;
    float acc[2][4][4];
    const float h = __ldg(hptr);

    if (sel == 0) {
        const float* B = txt + (long)b * MM * DD;
        gemm_main<0, 1>(A, B, MM, MM, DD, rowBase, colBase, sm, acc);
        const float* base = vis + (long)b * NN * DD;
        float* C = outv + (long)b * NN * DD;
#pragma unroll
        for (int mt = 0; mt < 2; mt++) {
            int r0 = rowBase + wm * 32 + mt * 16 + g;
            float s0 = h / rowsum[b * NN + r0];
            float s1 = h / rowsum[b * NN + r0 + 8];
#pragma unroll
            for (int nt = 0; nt < 4; nt++) {
                int col = colBase + wn * 32 + nt * 8 + 2 * q;
                float2 b0 = *(const float2*)(base + (long)r0 * DD + col);
                float2 b1 = *(const float2*)(base + (long)(r0 + 8) * DD + col);
                *(float2*)(C + (long)r0 * DD + col) =
                    make_float2(b0.x + s0 * acc[mt][nt][0], b0.y + s0 * acc[mt][nt][1]);
                *(float2*)(C + (long)(r0 + 8) * DD + col) =
                    make_float2(b1.x + s1 * acc[mt][nt][2], b1.y + s1 * acc[mt][nt][3]);
            }
        }
    } else {
        const float* B = vsc + (long)b * NN * DD;
        gemm_main<1, 1>(A, B, NN, MM, DD, rowBase, colBase, sm, acc);
        const float* base = txt + (long)b * MM * DD;
        float* C = outt + (long)b * MM * DD;
#pragma unroll
        for (int mt = 0; mt < 2; mt++) {
            int r0 = rowBase + wm * 32 + mt * 16 + g;
#pragma unroll
            for (int nt = 0; nt < 4; nt++) {
                int col = colBase + wn * 32 + nt * 8 + 2 * q;
                float2 b0 = *(const float2*)(base + (long)r0 * DD + col);
                float2 b1 = *(const float2*)(base + (long)(r0 + 8) * DD + col);
                *(float2*)(C + (long)r0 * DD + col) =
                    make_float2(b0.x + h * acc[mt][nt][0], b0.y + h * acc[mt][nt][1]);
                *(float2*)(C + (long)(r0 + 8) * DD + col) =
                    make_float2(b1.x + h * acc[mt][nt][2], b1.y + h * acc[mt][nt][3]);
            }
        }
    }
}

// ---------------------------------------------------------------------------
extern "C" void kernel_launch(void* const* d_in, const int* in_sizes, int n_in,
                              void* d_out, int out_size)
{
    (void)in_sizes; (void)n_in; (void)out_size;

    const float* vision = (const float*)d_in[0];
    const float* text   = (const float*)d_in[1];
    const float* Wv     = (const float*)d_in[2];
    const float* bv     = (const float*)d_in[3];
    const float* Wt     = (const float*)d_in[4];
    const float* bt     = (const float*)d_in[5];
    const float* hp     = (const float*)d_in[6];

    float* outv = (float*)d_out;
    float* outt = outv + (size_t)BB * NN * DD;

    float* scr = nullptr;
    cudaGetSymbolAddress((void**)&scr, g_scratch);
    float* Fv = scr + OFF_FV;
    float* Ft = scr + OFF_FT;
    float* E  = scr + OFF_E;
    float* RS = scr + OFF_RS;
    float* VS = scr + OFF_VS;

    // 1) Projections + quat features (also zeroes rowsum)
    proj_k<<<dim3(DD / 64, RTOT / 64, 2), 128>>>(vision, text, Wv, Wt, bv, bt,
                                                 Fv, Ft, RS);
    // 2) Score GEMM + exp + rowsums
    score_k<<<dim3(MM / 64, NN / 64, BB), 128>>>(Fv, Ft, E, RS);
    // 3) v' = vision / rowsum
    vscale_k<<<RTOT * DD / 4 / 128, 128>>>((const float4*)vision, RS, (float4*)VS);
    // 4) Both outputs in one launch
    out_k<<<dim3(DD / 64, NN / 64, 4), 128>>>(E, vision, text, VS, RS, hp,
                                              outv, outt);
}

// round 5
// speedup vs baseline: 3.1505x; 1.0103x over previous
#include <cuda_runtime.h>
#include <cstdint>
#include <math.h>

// Problem shapes (fixed by dataset)
#define BB 2
#define NN 512
#define MM 512
#define DD 256
#define KF 640            // heads * 10 symmetric features
#define RTOT (BB*NN)      // 1024 projection rows

// Scratch
#define OFF_FV 0
#define OFF_FT (OFF_FV + (size_t)RTOT*KF)
#define OFF_E  (OFF_FT + (size_t)RTOT*KF)
#define OFF_RS (OFF_E + (size_t)BB*NN*MM)
#define OFF_VS (OFF_RS + (size_t)RTOT)
#define SCRATCH_FLOATS (OFF_VS + (size_t)RTOT*DD)

__device__ __align__(16) float g_scratch[SCRATCH_FLOATS];

__device__ __forceinline__ void cp16(uint32_t dst, const void* src) {
    asm volatile("cp.async.ca.shared.global [%0], [%1], 16;\n" :: "r"(dst), "l"(src));
}
__device__ __forceinline__ void cp_commit() {
    asm volatile("cp.async.commit_group;\n");
}
template <int N> __device__ __forceinline__ void cp_wait() {
    asm volatile("cp.async.wait_group %0;\n" :: "n"(N));
}

// Pure register MMA — NOT volatile, so ptxas may interleave with LDS.
__device__ __forceinline__ void mma_tf32(float acc[4], const unsigned a[4],
                                         const unsigned b[2]) {
    asm("mma.sync.aligned.m16n8k8.row.col.f32.tf32.tf32.f32 "
        "{%0,%1,%2,%3},{%4,%5,%6,%7},{%8,%9},{%0,%1,%2,%3};"
        : "+f"(acc[0]), "+f"(acc[1]), "+f"(acc[2]), "+f"(acc[3])
        : "r"(a[0]), "r"(a[1]), "r"(a[2]), "r"(a[3]),
          "r"(b[0]), "r"(b[1]));
}

#define TILEF 2304   // floats per tile (64*36 == 32*72)
struct SmemT { float ab[2][2][TILEF]; };   // [stage][0=A,1=B]

// ---------------------------------------------------------------------------
// Shared tf32 MMA mainloop. C tile 64x64, BK=32, 128 threads (2x2 warps,
// 32x32 per warp), 2-stage cp.async double buffer, register-level fragment
// double buffering (LDS of slice ks+1 overlapped with MMAs of slice ks).
//   Lay==0: operand k-contiguous (X(i,k)=X[i*ld+k]) -> smem [i][pitch 36]
//   Lay==1: operand i-contiguous (X(i,k)=X[k*ld+i]) -> smem [k][pitch 72]
// ---------------------------------------------------------------------------
template <int ALay, int BLay>
__device__ __forceinline__ void gemm_main(
    const float* __restrict__ A, const float* __restrict__ B,
    int Kdim, int lda, int ldb, int rowBase, int colBase,
    SmemT& sm, float acc[2][4][4])
{
    const int tid  = threadIdx.x;
    const int lane = tid & 31;
    const int wid  = tid >> 5;
    const int wm   = wid >> 1;
    const int wn   = wid & 1;
    const int g    = lane >> 2;
    const int q    = lane & 3;

#pragma unroll
    for (int mt = 0; mt < 2; mt++)
#pragma unroll
        for (int nt = 0; nt < 4; nt++)
#pragma unroll
            for (int r = 0; r < 4; r++) acc[mt][nt][r] = 0.0f;

    auto fillA = [&](int st, int k0) {
        uint32_t base = (uint32_t)__cvta_generic_to_shared(&sm.ab[st][0][0]);
        if (ALay == 0) {
#pragma unroll
            for (int j = 0; j < 4; j++) {
                int idx = tid + 128 * j;
                int r = idx >> 3, ch = idx & 7;
                cp16(base + (r * 36 + ch * 4) * 4,
                     A + (long)(rowBase + r) * lda + k0 + ch * 4);
            }
        } else {
#pragma unroll
            for (int j = 0; j < 4; j++) {
                int idx = tid + 128 * j;
                int k = idx >> 4, ch = idx & 15;
                cp16(base + (k * 72 + ch * 4) * 4,
                     A + (long)(k0 + k) * lda + rowBase + ch * 4);
            }
        }
    };
    auto fillB = [&](int st, int k0) {
        uint32_t base = (uint32_t)__cvta_generic_to_shared(&sm.ab[st][1][0]);
        if (BLay == 0) {
#pragma unroll
            for (int j = 0; j < 4; j++) {
                int idx = tid + 128 * j;
                int r = idx >> 3, ch = idx & 7;
                cp16(base + (r * 36 + ch * 4) * 4,
                     B + (long)(colBase + r) * ldb + k0 + ch * 4);
            }
        } else {
#pragma unroll
            for (int j = 0; j < 4; j++) {
                int idx = tid + 128 * j;
                int k = idx >> 4, ch = idx & 15;
                cp16(base + (k * 72 + ch * 4) * 4,
                     B + (long)(k0 + k) * ldb + colBase + ch * 4);
            }
        }
    };

    const int r0a = wm * 32;       // warp's first A row
    const int c0b = wn * 32;       // warp's first B col

    const int niter = Kdim >> 5;
    fillA(0, 0);
    fillB(0, 0);
    cp_commit();

    for (int i = 0; i < niter; i++) {
        const int cur = i & 1;
        if (i + 1 < niter) {
            fillA(cur ^ 1, (i + 1) * 32);
            fillB(cur ^ 1, (i + 1) * 32);
            cp_commit();
            cp_wait<1>();
        } else {
            cp_wait<0>();
        }
        __syncthreads();

        const unsigned* fA = (const unsigned*)&sm.ab[cur][0][0];
        const unsigned* fB = (const unsigned*)&sm.ab[cur][1][0];

        // fragment register double buffers
        unsigned a[2][2][4], b[2][4][2];

        auto loadFrag = [&](int ks, unsigned aB[2][4], unsigned bB[4][2]) {
#pragma unroll
            for (int mt = 0; mt < 2; mt++) {
                int r0 = r0a + mt * 16;
                if (ALay == 0) {
                    aB[mt][0] = fA[(r0 + g)     * 36 + ks * 8 + q];
                    aB[mt][1] = fA[(r0 + 8 + g) * 36 + ks * 8 + q];
                    aB[mt][2] = fA[(r0 + g)     * 36 + ks * 8 + 4 + q];
                    aB[mt][3] = fA[(r0 + 8 + g) * 36 + ks * 8 + 4 + q];
                } else {
                    aB[mt][0] = fA[(ks * 8 + q)     * 72 + r0 + g];
                    aB[mt][1] = fA[(ks * 8 + q)     * 72 + r0 + 8 + g];
                    aB[mt][2] = fA[(ks * 8 + 4 + q) * 72 + r0 + g];
                    aB[mt][3] = fA[(ks * 8 + 4 + q) * 72 + r0 + 8 + g];
                }
            }
#pragma unroll
            for (int nt = 0; nt < 4; nt++) {
                int c0 = c0b + nt * 8;
                if (BLay == 0) {
                    bB[nt][0] = fB[(c0 + g) * 36 + ks * 8 + q];
                    bB[nt][1] = fB[(c0 + g) * 36 + ks * 8 + 4 + q];
                } else {
                    bB[nt][0] = fB[(ks * 8 + q)     * 72 + c0 + g];
                    bB[nt][1] = fB[(ks * 8 + 4 + q) * 72 + c0 + g];
                }
            }
        };

        loadFrag(0, a[0], b[0]);
#pragma unroll
        for (int ks = 0; ks < 4; ks++) {
            const int pb = ks & 1;
            if (ks < 3) loadFrag(ks + 1, a[pb ^ 1], b[pb ^ 1]);
#pragma unroll
            for (int mt = 0; mt < 2; mt++)
#pragma unroll
                for (int nt = 0; nt < 4; nt++)
                    mma_tf32(acc[mt][nt], a[pb][mt], b[pb][nt]);
        }
        __syncthreads();
    }
}

// ---------------------------------------------------------------------------
// 1) Combined projection: z=0 vision/Wv/bv (fmult 1), z=1 text/Wt/bt (fmult 2).
//    Epilogue: +bias, quat-normalize, 10-feature expansion into Fout (KF wide).
//    Linear CTA ids 0..3 also zero the rowsum array for the score pass.
// ---------------------------------------------------------------------------
__global__ void __launch_bounds__(128)
proj_k(const float* __restrict__ vis, const float* __restrict__ txt,
       const float* __restrict__ Wv, const float* __restrict__ Wt,
       const float* __restrict__ bv, const float* __restrict__ bt,
       float* __restrict__ Fv, float* __restrict__ Ft,
       float* __restrict__ rowsum)
{
    __shared__ __align__(16) union { SmemT t; float Cs[64][68]; } sm;

    const int z = blockIdx.z;
    const int linear = blockIdx.x + blockIdx.y * gridDim.x +
                       z * gridDim.x * gridDim.y;
    if (linear < 4) {
        rowsum[linear * 256 + threadIdx.x] = 0.0f;
        rowsum[linear * 256 + 128 + threadIdx.x] = 0.0f;
    }

    const float* A   = z ? txt : vis;
    const float* W   = z ? Wt : Wv;
    const float* bia = z ? bt : bv;
    float* Fout      = z ? Ft : Fv;
    const float fmult = z ? 2.0f : 1.0f;

    const int rowBase = blockIdx.y * 64;
    const int colBase = blockIdx.x * 64;
    const int tid = threadIdx.x;
    const int lane = tid & 31, wid = tid >> 5;
    const int wm = wid >> 1, wn = wid & 1, g = lane >> 2, q = lane & 3;

    float acc[2][4][4];
    gemm_main<0, 0>(A, W, DD, DD, DD, rowBase, colBase, sm.t, acc);

#pragma unroll
    for (int mt = 0; mt < 2; mt++)
#pragma unroll
        for (int nt = 0; nt < 4; nt++) {
            int lr = wm * 32 + mt * 16 + g;
            int lc = wn * 32 + nt * 8 + 2 * q;
            sm.Cs[lr][lc]         = acc[mt][nt][0];
            sm.Cs[lr][lc + 1]     = acc[mt][nt][1];
            sm.Cs[lr + 8][lc]     = acc[mt][nt][2];
            sm.Cs[lr + 8][lc + 1] = acc[mt][nt][3];
        }
    __syncthreads();
#pragma unroll
    for (int c = 0; c < 8; c++) {
        int qi = tid + 128 * c;       // 1024 quats per CTA
        int lr = qi >> 4;
        int hq = qi & 15;
        float4 bb = *(const float4*)(bia + colBase + hq * 4);
        float w  = sm.Cs[lr][hq * 4 + 0] + bb.x;
        float x  = sm.Cs[lr][hq * 4 + 1] + bb.y;
        float y  = sm.Cs[lr][hq * 4 + 2] + bb.z;
        float zz = sm.Cs[lr][hq * 4 + 3] + bb.w;
        float inv = 1.0f / (sqrtf(w * w + x * x + y * y + zz * zz) + 1e-8f);
        w *= inv; x *= inv; y *= inv; zz *= inv;
        float* o = Fout + (long)(rowBase + lr) * KF + ((colBase >> 2) + hq) * 10;
        o[0] = w * w;
        o[1] = fmult * w * x;
        o[2] = fmult * w * y;
        o[3] = fmult * w * zz;
        o[4] = x * x;
        o[5] = fmult * x * y;
        o[6] = fmult * x * zz;
        o[7] = y * y;
        o[8] = fmult * y * zz;
        o[9] = zz * zz;
    }
}

// ---------------------------------------------------------------------------
// 2) Score GEMM + exp epilogue + rowsum atomics.
//    E[b,n,m] = exp( (Fv.Ft)/1024 ), rowsum[b*NN+n] += row partials.
//    (Logits are in [0, 1/16] so max-subtraction is unnecessary.)
// ---------------------------------------------------------------------------
__global__ void __launch_bounds__(128)
score_k(const float* __restrict__ Fv, const float* __restrict__ Ft,
        float* __restrict__ E, float* __restrict__ rowsum)
{
    __shared__ __align__(16) SmemT sm;
    const int z = blockIdx.z;
    const float* A = Fv + (long)z * NN * KF;
    const float* B = Ft + (long)z * MM * KF;
    float* C = E + (long)z * NN * MM;

    const int rowBase = blockIdx.y * 64;
    const int colBase = blockIdx.x * 64;
    const int tid = threadIdx.x;
    const int lane = tid & 31, wid = tid >> 5;
    const int wm = wid >> 1, wn = wid & 1, g = lane >> 2, q = lane & 3;

    float acc[2][4][4];
    gemm_main<0, 0>(A, B, KF, KF, KF, rowBase, colBase, sm, acc);

    const float SC = 1.0f / 1024.0f;
    float rsum[2][2] = {{0.f, 0.f}, {0.f, 0.f}};
#pragma unroll
    for (int mt = 0; mt < 2; mt++)
#pragma unroll
        for (int nt = 0; nt < 4; nt++) {
            int row = rowBase + wm * 32 + mt * 16 + g;
            int col = colBase + wn * 32 + nt * 8 + 2 * q;
            float e0 = __expf(acc[mt][nt][0] * SC);
            float e1 = __expf(acc[mt][nt][1] * SC);
            float e2 = __expf(acc[mt][nt][2] * SC);
            float e3 = __expf(acc[mt][nt][3] * SC);
            *(float2*)(C + (long)row * MM + col)       = make_float2(e0, e1);
            *(float2*)(C + (long)(row + 8) * MM + col) = make_float2(e2, e3);
            rsum[mt][0] += e0 + e1;
            rsum[mt][1] += e2 + e3;
        }
    // quad-reduce (lanes sharing g hold the same rows)
#pragma unroll
    for (int mt = 0; mt < 2; mt++)
#pragma unroll
        for (int hh = 0; hh < 2; hh++) {
            float v = rsum[mt][hh];
            v += __shfl_xor_sync(0xffffffffu, v, 1);
            v += __shfl_xor_sync(0xffffffffu, v, 2);
            if (q == 0) {
                int row = rowBase + wm * 32 + mt * 16 + hh * 8 + g;
                atomicAdd(&rowsum[z * NN + row], v);
            }
        }
}

// ---------------------------------------------------------------------------
// 3) vscale: v'[r,d] = vision[r,d] / rowsum[r]   (r = global projection row)
// ---------------------------------------------------------------------------
__global__ void __launch_bounds__(128)
vscale_k(const float4* __restrict__ vis, const float* __restrict__ rowsum,
         float4* __restrict__ vs)
{
    int idx = blockIdx.x * 128 + threadIdx.x;   // RTOT*DD/4 = 65536
    int row = idx >> 6;                          // DD/4 = 64 float4 per row
    float inv = 1.0f / rowsum[row];
    float4 v = vis[idx];
    v.x *= inv; v.y *= inv; v.z *= inv; v.w *= inv;
    vs[idx] = v;
}

// ---------------------------------------------------------------------------
// 4) Combined output GEMM. z=(sel<<1)|b.
//    sel=0: outv[b] = vision + (h/rs[row]) * E[b] @ text[b]        (A lay0, B lay1)
//    sel=1: outt[b] = text   +  h          * E[b]^T @ v'[b]        (A lay1, B lay1)
// ---------------------------------------------------------------------------
__global__ void __launch_bounds__(128)
out_k(const float* __restrict__ E, const float* __restrict__ vis,
      const float* __restrict__ txt, const float* __restrict__ vsc,
      const float* __restrict__ rowsum, const float* __restrict__ hptr,
      float* __restrict__ outv, float* __restrict__ outt)
{
    __shared__ __align__(16) SmemT sm;
    const int zz = blockIdx.z;
    const int b = zz & 1;
    const int sel = zz >> 1;

    const int rowBase = blockIdx.y * 64;
    const int colBase = blockIdx.x * 64;
    const int tid = threadIdx.x;
    const int lane = tid & 31, wid = tid >> 5;
    const int wm = wid >> 1, wn = wid & 1, g = lane >> 2, q = lane & 3;

    const float* A = E + (long)b * NN * MM;
    float acc[2][4][4];
    const float h = __ldg(hptr);

    if (sel == 0) {
        const float* B = txt + (long)b * MM * DD;
        gemm_main<0, 1>(A, B, MM, MM, DD, rowBase, colBase, sm, acc);
        const float* base = vis + (long)b * NN * DD;
        float* C = outv + (long)b * NN * DD;
#pragma unroll
        for (int mt = 0; mt < 2; mt++) {
            int r0 = rowBase + wm * 32 + mt * 16 + g;
            float s0 = h / rowsum[b * NN + r0];
            float s1 = h / rowsum[b * NN + r0 + 8];
#pragma unroll
            for (int nt = 0; nt < 4; nt++) {
                int col = colBase + wn * 32 + nt * 8 + 2 * q;
                float2 b0 = *(const float2*)(base + (long)r0 * DD + col);
                float2 b1 = *(const float2*)(base + (long)(r0 + 8) * DD + col);
                *(float2*)(C + (long)r0 * DD + col) =
                    make_float2(b0.x + s0 * acc[mt][nt][0], b0.y + s0 * acc[mt][nt][1]);
                *(float2*)(C + (long)(r0 + 8) * DD + col) =
                    make_float2(b1.x + s1 * acc[mt][nt][2], b1.y + s1 * acc[mt][nt][3]);
            }
        }
    } else {
        const float* B = vsc + (long)b * NN * DD;
        gemm_main<1, 1>(A, B, NN, MM, DD, rowBase, colBase, sm, acc);
        const float* base = txt + (long)b * MM * DD;
        float* C = outt + (long)b * MM * DD;
#pragma unroll
        for (int mt = 0; mt < 2; mt++) {
            int r0 = rowBase + wm * 32 + mt * 16 + g;
#pragma unroll
            for (int nt = 0; nt < 4; nt++) {
                int col = colBase + wn * 32 + nt * 8 + 2 * q;
                float2 b0 = *(const float2*)(base + (long)r0 * DD + col);
                float2 b1 = *(const float2*)(base + (long)(r0 + 8) * DD + col);
                *(float2*)(C + (long)r0 * DD + col) =
                    make_float2(b0.x + h * acc[mt][nt][0], b0.y + h * acc[mt][nt][1]);
                *(float2*)(C + (long)(r0 + 8) * DD + col) =
                    make_float2(b1.x + h * acc[mt][nt][2], b1.y + h * acc[mt][nt][3]);
            }
        }
    }
}

// ---------------------------------------------------------------------------
extern "C" void kernel_launch(void* const* d_in, const int* in_sizes, int n_in,
                              void* d_out, int out_size)
{
    (void)in_sizes; (void)n_in; (void)out_size;

    const float* vision = (const float*)d_in[0];
    const float* text   = (const float*)d_in[1];
    const float* Wv     = (const float*)d_in[2];
    const float* bv     = (const float*)d_in[3];
    const float* Wt     = (const float*)d_in[4];
    const float* bt     = (const float*)d_in[5];
    const float* hp     = (const float*)d_in[6];

    float* outv = (float*)d_out;
    float* outt = outv + (size_t)BB * NN * DD;

    float* scr = nullptr;
    cudaGetSymbolAddress((void**)&scr, g_scratch);
    float* Fv = scr + OFF_FV;
    float* Ft = scr + OFF_FT;
    float* E  = scr + OFF_E;
    float* RS = scr + OFF_RS;
    float* VS = scr + OFF_VS;

    // 1) Projections + quat features (also zeroes rowsum)
    proj_k<<<dim3(DD / 64, RTOT / 64, 2), 128>>>(vision, text, Wv, Wt, bv, bt,
                                                 Fv, Ft, RS);
    // 2) Score GEMM + exp + rowsums
    score_k<<<dim3(MM / 64, NN / 64, BB), 128>>>(Fv, Ft, E, RS);
    // 3) v' = vision / rowsum
    vscale_k<<<RTOT * DD / 4 / 128, 128>>>((const float4*)vision, RS, (float4*)VS);
    // 4) Both outputs in one launch
    out_k<<<dim3(DD / 64, NN / 64, 4), 128>>>(E, vision, text, VS, RS, hp,
                                              outv, outt);
}

// round 6
// speedup vs baseline: 3.3009x; 1.0477x over previous
#include <cuda_runtime.h>
#include <cstdint>
#include <math.h>

// Problem shapes (fixed by dataset)
#define BB 2
#define NN 512
#define MM 512
#define DD 256
#define KF 640            // heads * 10 symmetric features
#define RTOT (BB*NN)      // 1024 projection rows

// Scratch
#define OFF_FV 0
#define OFF_FT (OFF_FV + (size_t)RTOT*KF)
#define OFF_E  (OFF_FT + (size_t)RTOT*KF)
#define OFF_RS (OFF_E + (size_t)BB*NN*MM)
#define OFF_VS (OFF_RS + (size_t)RTOT)
#define SCRATCH_FLOATS (OFF_VS + (size_t)RTOT*DD)

__device__ __align__(16) float g_scratch[SCRATCH_FLOATS];

__device__ __forceinline__ void cp16(uint32_t dst, const void* src) {
    asm volatile("cp.async.ca.shared.global [%0], [%1], 16;\n" :: "r"(dst), "l"(src));
}
__device__ __forceinline__ void cp_commit() {
    asm volatile("cp.async.commit_group;\n");
}
template <int N> __device__ __forceinline__ void cp_wait() {
    asm volatile("cp.async.wait_group %0;\n" :: "n"(N));
}

// Pure register MMA — NOT volatile, so ptxas may interleave with LDS.
__device__ __forceinline__ void mma_tf32(float acc[4], const unsigned a[4],
                                         const unsigned b[2]) {
    asm("mma.sync.aligned.m16n8k8.row.col.f32.tf32.tf32.f32 "
        "{%0,%1,%2,%3},{%4,%5,%6,%7},{%8,%9},{%0,%1,%2,%3};"
        : "+f"(acc[0]), "+f"(acc[1]), "+f"(acc[2]), "+f"(acc[3])
        : "r"(a[0]), "r"(a[1]), "r"(a[2]), "r"(b[0]) /*placeholder*/, "r"(a[3]), "r"(b[1]));
}

#define TILEF 2304            // floats per tile (64*36 == 32*72)
#define STAGEF (2*TILEF)      // A+B per stage
#define STAGES 4
#define DSMEM_BYTES (STAGES*STAGEF*4)   // 73728

// ---------------------------------------------------------------------------
// Shared tf32 MMA mainloop. C tile 64x64, BK=32, 128 threads (2x2 warps,
// 32x32 per warp), 4-stage cp.async ring (prefetch distance 3), ONE
// __syncthreads per iteration, register fragment double buffering.
//   Lay==0: operand k-contiguous (X(i,k)=X[i*ld+k]) -> smem [i][pitch 36]
//   Lay==1: operand i-contiguous (X(i,k)=X[k*ld+i]) -> smem [k][pitch 72]
// ---------------------------------------------------------------------------
template <int ALay, int BLay>
__device__ __forceinline__ void gemm_main(
    const float* __restrict__ A, const float* __restrict__ B,
    int Kdim, int lda, int ldb, int rowBase, int colBase,
    float* __restrict__ dsm, float acc[2][4][4])
{
    const int tid  = threadIdx.x;
    const int lane = tid & 31;
    const int wid  = tid >> 5;
    const int wm   = wid >> 1;
    const int wn   = wid & 1;
    const int g    = lane >> 2;
    const int q    = lane & 3;

#pragma unroll
    for (int mt = 0; mt < 2; mt++)
#pragma unroll
        for (int nt = 0; nt < 4; nt++)
#pragma unroll
            for (int r = 0; r < 4; r++) acc[mt][nt][r] = 0.0f;

    auto fillA = [&](int st, int k0) {
        uint32_t base = (uint32_t)__cvta_generic_to_shared(dsm + st * STAGEF);
        if (ALay == 0) {
#pragma unroll
            for (int j = 0; j < 4; j++) {
                int idx = tid + 128 * j;
                int r = idx >> 3, ch = idx & 7;
                cp16(base + (r * 36 + ch * 4) * 4,
                     A + (long)(rowBase + r) * lda + k0 + ch * 4);
            }
        } else {
#pragma unroll
            for (int j = 0; j < 4; j++) {
                int idx = tid + 128 * j;
                int k = idx >> 4, ch = idx & 15;
                cp16(base + (k * 72 + ch * 4) * 4,
                     A + (long)(k0 + k) * lda + rowBase + ch * 4);
            }
        }
    };
    auto fillB = [&](int st, int k0) {
        uint32_t base = (uint32_t)__cvta_generic_to_shared(dsm + st * STAGEF + TILEF);
        if (BLay == 0) {
#pragma unroll
            for (int j = 0; j < 4; j++) {
                int idx = tid + 128 * j;
                int r = idx >> 3, ch = idx & 7;
                cp16(base + (r * 36 + ch * 4) * 4,
                     B + (long)(colBase + r) * ldb + k0 + ch * 4);
            }
        } else {
#pragma unroll
            for (int j = 0; j < 4; j++) {
                int idx = tid + 128 * j;
                int k = idx >> 4, ch = idx & 15;
                cp16(base + (k * 72 + ch * 4) * 4,
                     B + (long)(k0 + k) * ldb + colBase + ch * 4);
            }
        }
    };

    const int r0a = wm * 32;       // warp's first A row
    const int c0b = wn * 32;       // warp's first B col

    const int niter = Kdim >> 5;

    // Prologue: prefetch STAGES-1 stages, one commit group per stage.
#pragma unroll
    for (int s = 0; s < STAGES - 1; s++) {
        if (s < niter) { fillA(s, s * 32); fillB(s, s * 32); }
        cp_commit();
    }

    for (int i = 0; i < niter; i++) {
        const int cur = i & (STAGES - 1);
        cp_wait<STAGES - 2>();        // stage i's fills complete
        __syncthreads();              // all warps done reading stage (i-1)&3

        const int nf = i + STAGES - 1;
        if (nf < niter) { fillA(nf & (STAGES - 1), nf * 32);
                          fillB(nf & (STAGES - 1), nf * 32); }
        cp_commit();

        const unsigned* fA = (const unsigned*)(dsm + cur * STAGEF);
        const unsigned* fB = (const unsigned*)(dsm + cur * STAGEF + TILEF);

        unsigned a[2][2][4], b[2][4][2];

        auto loadFrag = [&](int ks, unsigned aB[2][4], unsigned bB[4][2]) {
#pragma unroll
            for (int mt = 0; mt < 2; mt++) {
                int r0 = r0a + mt * 16;
                if (ALay == 0) {
                    aB[mt][0] = fA[(r0 + g)     * 36 + ks * 8 + q];
                    aB[mt][1] = fA[(r0 + 8 + g) * 36 + ks * 8 + q];
                    aB[mt][2] = fA[(r0 + g)     * 36 + ks * 8 + 4 + q];
                    aB[mt][3] = fA[(r0 + 8 + g) * 36 + ks * 8 + 4 + q];
                } else {
                    aB[mt][0] = fA[(ks * 8 + q)     * 72 + r0 + g];
                    aB[mt][1] = fA[(ks * 8 + q)     * 72 + r0 + 8 + g];
                    aB[mt][2] = fA[(ks * 8 + 4 + q) * 72 + r0 + g];
                    aB[mt][3] = fA[(ks * 8 + 4 + q) * 72 + r0 + 8 + g];
                }
            }
#pragma unroll
            for (int nt = 0; nt < 4; nt++) {
                int c0 = c0b + nt * 8;
                if (BLay == 0) {
                    bB[nt][0] = fB[(c0 + g) * 36 + ks * 8 + q];
                    bB[nt][1] = fB[(c0 + g) * 36 + ks * 8 + 4 + q];
                } else {
                    bB[nt][0] = fB[(ks * 8 + q)     * 72 + c0 + g];
                    bB[nt][1] = fB[(ks * 8 + 4 + q) * 72 + c0 + g];
                }
            }
        };

        loadFrag(0, a[0], b[0]);
#pragma unroll
        for (int ks = 0; ks < 4; ks++) {
            const int pb = ks & 1;
            if (ks < 3) loadFrag(ks + 1, a[pb ^ 1], b[pb ^ 1]);
#pragma unroll
            for (int mt = 0; mt < 2; mt++)
#pragma unroll
                for (int nt = 0; nt < 4; nt++) {
                    asm("mma.sync.aligned.m16n8k8.row.col.f32.tf32.tf32.f32 "
                        "{%0,%1,%2,%3},{%4,%5,%6,%7},{%8,%9},{%0,%1,%2,%3};"
                        : "+f"(acc[mt][nt][0]), "+f"(acc[mt][nt][1]),
                          "+f"(acc[mt][nt][2]), "+f"(acc[mt][nt][3])
                        : "r"(a[pb][mt][0]), "r"(a[pb][mt][1]),
                          "r"(a[pb][mt][2]), "r"(a[pb][mt][3]),
                          "r"(b[pb][nt][0]), "r"(b[pb][nt][1]));
                }
        }
    }
    __syncthreads();   // protect smem reuse by epilogues
}

// ---------------------------------------------------------------------------
// 1) Combined projection: z=0 vision/Wv/bv (fmult 1), z=1 text/Wt/bt (fmult 2).
//    Epilogue: +bias, quat-normalize, 10-feature expansion into Fout (KF wide).
//    Linear CTA ids 0..3 also zero the rowsum array for the score pass.
// ---------------------------------------------------------------------------
__global__ void __launch_bounds__(128)
proj_k(const float* __restrict__ vis, const float* __restrict__ txt,
       const float* __restrict__ Wv, const float* __restrict__ Wt,
       const float* __restrict__ bv, const float* __restrict__ bt,
       float* __restrict__ Fv, float* __restrict__ Ft,
       float* __restrict__ rowsum)
{
    extern __shared__ __align__(16) float dsm[];

    const int z = blockIdx.z;
    const int linear = blockIdx.x + blockIdx.y * gridDim.x +
                       z * gridDim.x * gridDim.y;
    if (linear < 4) {
        rowsum[linear * 256 + threadIdx.x] = 0.0f;
        rowsum[linear * 256 + 128 + threadIdx.x] = 0.0f;
    }

    const float* A   = z ? txt : vis;
    const float* W   = z ? Wt : Wv;
    const float* bia = z ? bt : bv;
    float* Fout      = z ? Ft : Fv;
    const float fmult = z ? 2.0f : 1.0f;

    const int rowBase = blockIdx.y * 64;
    const int colBase = blockIdx.x * 64;
    const int tid = threadIdx.x;
    const int lane = tid & 31, wid = tid >> 5;
    const int wm = wid >> 1, wn = wid & 1, g = lane >> 2, q = lane & 3;

    float acc[2][4][4];
    gemm_main<0, 0>(A, W, DD, DD, DD, rowBase, colBase, dsm, acc);

    float (*Cs)[68] = (float (*)[68])dsm;    // 64x68 staging (reuses ring smem)
#pragma unroll
    for (int mt = 0; mt < 2; mt++)
#pragma unroll
        for (int nt = 0; nt < 4; nt++) {
            int lr = wm * 32 + mt * 16 + g;
            int lc = wn * 32 + nt * 8 + 2 * q;
            Cs[lr][lc]         = acc[mt][nt][0];
            Cs[lr][lc + 1]     = acc[mt][nt][1];
            Cs[lr + 8][lc]     = acc[mt][nt][2];
            Cs[lr + 8][lc + 1] = acc[mt][nt][3];
        }
    __syncthreads();
#pragma unroll
    for (int c = 0; c < 8; c++) {
        int qi = tid + 128 * c;       // 1024 quats per CTA
        int lr = qi >> 4;
        int hq = qi & 15;
        float4 bb = *(const float4*)(bia + colBase + hq * 4);
        float w  = Cs[lr][hq * 4 + 0] + bb.x;
        float x  = Cs[lr][hq * 4 + 1] + bb.y;
        float y  = Cs[lr][hq * 4 + 2] + bb.z;
        float zz = Cs[lr][hq * 4 + 3] + bb.w;
        float inv = 1.0f / (sqrtf(w * w + x * x + y * y + zz * zz) + 1e-8f);
        w *= inv; x *= inv; y *= inv; zz *= inv;
        float* o = Fout + (long)(rowBase + lr) * KF + ((colBase >> 2) + hq) * 10;
        o[0] = w * w;
        o[1] = fmult * w * x;
        o[2] = fmult * w * y;
        o[3] = fmult * w * zz;
        o[4] = x * x;
        o[5] = fmult * x * y;
        o[6] = fmult * x * zz;
        o[7] = y * y;
        o[8] = fmult * y * zz;
        o[9] = zz * zz;
    }
}

// ---------------------------------------------------------------------------
// 2) Score GEMM + exp epilogue + rowsum atomics.
//    E[b,n,m] = exp( (Fv.Ft)/1024 ), rowsum[b*NN+n] += row partials.
//    (Logits are in [0, 1/16] so max-subtraction is unnecessary.)
// ---------------------------------------------------------------------------
__global__ void __launch_bounds__(128)
score_k(const float* __restrict__ Fv, const float* __restrict__ Ft,
        float* __restrict__ E, float* __restrict__ rowsum)
{
    extern __shared__ __align__(16) float dsm[];
    const int z = blockIdx.z;
    const float* A = Fv + (long)z * NN * KF;
    const float* B = Ft + (long)z * MM * KF;
    float* C = E + (long)z * NN * MM;

    const int rowBase = blockIdx.y * 64;
    const int colBase = blockIdx.x * 64;
    const int tid = threadIdx.x;
    const int lane = tid & 31, wid = tid >> 5;
    const int wm = wid >> 1, wn = wid & 1, g = lane >> 2, q = lane & 3;

    float acc[2][4][4];
    gemm_main<0, 0>(A, B, KF, KF, KF, rowBase, colBase, dsm, acc);

    const float SC = 1.0f / 1024.0f;
    float rsum[2][2] = {{0.f, 0.f}, {0.f, 0.f}};
#pragma unroll
    for (int mt = 0; mt < 2; mt++)
#pragma unroll
        for (int nt = 0; nt < 4; nt++) {
            int row = rowBase + wm * 32 + mt * 16 + g;
            int col = colBase + wn * 32 + nt * 8 + 2 * q;
            float e0 = __expf(acc[mt][nt][0] * SC);
            float e1 = __expf(acc[mt][nt][1] * SC);
            float e2 = __expf(acc[mt][nt][2] * SC);
            float e3 = __expf(acc[mt][nt][3] * SC);
            *(float2*)(C + (long)row * MM + col)       = make_float2(e0, e1);
            *(float2*)(C + (long)(row + 8) * MM + col) = make_float2(e2, e3);
            rsum[mt][0] += e0 + e1;
            rsum[mt][1] += e2 + e3;
        }
    // quad-reduce (lanes sharing g hold the same rows)
#pragma unroll
    for (int mt = 0; mt < 2; mt++)
#pragma unroll
        for (int hh = 0; hh < 2; hh++) {
            float v = rsum[mt][hh];
            v += __shfl_xor_sync(0xffffffffu, v, 1);
            v += __shfl_xor_sync(0xffffffffu, v, 2);
            if (q == 0) {
                int row = rowBase + wm * 32 + mt * 16 + hh * 8 + g;
                atomicAdd(&rowsum[z * NN + row], v);
            }
        }
}

// ---------------------------------------------------------------------------
// 3) vscale: v'[r,d] = vision[r,d] / rowsum[r]   (r = global projection row)
// ---------------------------------------------------------------------------
__global__ void __launch_bounds__(128)
vscale_k(const float4* __restrict__ vis, const float* __restrict__ rowsum,
         float4* __restrict__ vs)
{
    int idx = blockIdx.x * 128 + threadIdx.x;   // RTOT*DD/4 = 65536
    int row = idx >> 6;                          // DD/4 = 64 float4 per row
    float inv = 1.0f / rowsum[row];
    float4 v = vis[idx];
    v.x *= inv; v.y *= inv; v.z *= inv; v.w *= inv;
    vs[idx] = v;
}

// ---------------------------------------------------------------------------
// 4) Combined output GEMM. z=(sel<<1)|b.
//    sel=0: outv[b] = vision + (h/rs[row]) * E[b] @ text[b]        (A lay0, B lay1)
//    sel=1: outt[b] = text   +  h          * E[b]^T @ v'[b]        (A lay1, B lay1)
// ---------------------------------------------------------------------------
__global__ void __launch_bounds__(128)
out_k(const float* __restrict__ E, const float* __restrict__ vis,
      const float* __restrict__ txt, const float* __restrict__ vsc,
      const float* __restrict__ rowsum, const float* __restrict__ hptr,
      float* __restrict__ outv, float* __restrict__ outt)
{
    extern __shared__ __align__(16) float dsm[];
    const int zz = blockIdx.z;
    const int b = zz & 1;
    const int sel = zz >> 1;

    const int rowBase = blockIdx.y * 64;
    const int colBase = blockIdx.x * 64;
    const int tid = threadIdx.x;
    const int lane = tid & 31, wid = tid >> 5;
    const int wm = wid >> 1, wn = wid & 1, g = lane >> 2, q = lane & 3;

    const float* A = E + (long)b * NN * MM;
    float acc[2][4][4];
    const float h = __ldg(hptr);

    if (sel == 0) {
        const float* B = txt + (long)b * MM * DD;
        gemm_main<0, 1>(A, B, MM, MM, DD, rowBase, colBase, dsm, acc);
        const float* base = vis + (long)b * NN * DD;
        float* C = outv + (long)b * NN * DD;
#pragma unroll
        for (int mt = 0; mt < 2; mt++) {
            int r0 = rowBase + wm * 32 + mt * 16 + g;
            float s0 = h / rowsum[b * NN + r0];
            float s1 = h / rowsum[b * NN + r0 + 8];
#pragma unroll
            for (int nt = 0; nt < 4; nt++) {
                int col = colBase + wn * 32 + nt * 8 + 2 * q;
                float2 b0 = *(const float2*)(base + (long)r0 * DD + col);
                float2 b1 = *(const float2*)(base + (long)(r0 + 8) * DD + col);
                *(float2*)(C + (long)r0 * DD + col) =
                    make_float2(b0.x + s0 * acc[mt][nt][0], b0.y + s0 * acc[mt][nt][1]);
                *(float2*)(C + (long)(r0 + 8) * DD + col) =
                    make_float2(b1.x + s1 * acc[mt][nt][2], b1.y + s1 * acc[mt][nt][3]);
            }
        }
    } else {
        const float* B = vsc + (long)b * NN * DD;
        gemm_main<1, 1>(A, B, NN, MM, DD, rowBase, colBase, dsm, acc);
        const float* base = txt + (long)b * MM * DD;
        float* C = outt + (long)b * MM * DD;
#pragma unroll
        for (int mt = 0; mt < 2; mt++) {
            int r0 = rowBase + wm * 32 + mt * 16 + g;
#pragma unroll
            for (int nt = 0; nt < 4; nt++) {
                int col = colBase + wn * 32 + nt * 8 + 2 * q;
                float2 b0 = *(const float2*)(base + (long)r0 * DD + col);
                float2 b1 = *(const float2*)(base + (long)(r0 + 8) * DD + col);
                *(float2*)(C + (long)r0 * DD + col) =
                    make_float2(b0.x + h * acc[mt][nt][0], b0.y + h * acc[mt][nt][1]);
                *(float2*)(C + (long)(r0 + 8) * DD + col) =
                    make_float2(b1.x + h * acc[mt][nt][2], b1.y + h * acc[mt][nt][3]);
            }
        }
    }
}

// ---------------------------------------------------------------------------
extern "C" void kernel_launch(void* const* d_in, const int* in_sizes, int n_in,
                              void* d_out, int out_size)
{
    (void)in_sizes; (void)n_in; (void)out_size;

    const float* vision = (const float*)d_in[0];
    const float* text   = (const float*)d_in[1];
    const float* Wv     = (const float*)d_in[2];
    const float* bv     = (const float*)d_in[3];
    const float* Wt     = (const float*)d_in[4];
    const float* bt     = (const float*)d_in[5];
    const float* hp     = (const float*)d_in[6];

    float* outv = (float*)d_out;
    float* outt = outv + (size_t)BB * NN * DD;

    float* scr = nullptr;
    cudaGetSymbolAddress((void**)&scr, g_scratch);
    float* Fv = scr + OFF_FV;
    float* Ft = scr + OFF_FT;
    float* E  = scr + OFF_E;
    float* RS = scr + OFF_RS;
    float* VS = scr + OFF_VS;

    // Opt into >48KB dynamic smem (persistent per-function attribute; set on
    // the first, uncaptured call — no allocation, no stream op).
    cudaFuncSetAttribute(proj_k,  cudaFuncAttributeMaxDynamicSharedMemorySize, DSMEM_BYTES);
    cudaFuncSetAttribute(score_k, cudaFuncAttributeMaxDynamicSharedMemorySize, DSMEM_BYTES);
    cudaFuncSetAttribute(out_k,   cudaFuncAttributeMaxDynamicSharedMemorySize, DSMEM_BYTES);

    // 1) Projections + quat features (also zeroes rowsum)
    proj_k<<<dim3(DD / 64, RTOT / 64, 2), 128, DSMEM_BYTES>>>(
        vision, text, Wv, Wt, bv, bt, Fv, Ft, RS);
    // 2) Score GEMM + exp + rowsums
    score_k<<<dim3(MM / 64, NN / 64, BB), 128, DSMEM_BYTES>>>(Fv, Ft, E, RS);
    // 3) v' = vision / rowsum
    vscale_k<<<RTOT * DD / 4 / 128, 128>>>((const float4*)vision, RS, (float4*)VS);
    // 4) Both outputs in one launch
    out_k<<<dim3(DD / 64, NN / 64, 4), 128, DSMEM_BYTES>>>(
        E, vision, text, VS, RS, hp, outv, outt);
}